// round 1
// baseline (speedup 1.0000x reference)
#include <cuda_runtime.h>
#include <cuda_bf16.h>
#include <cstddef>

// ---------------- scratch (no cudaMalloc allowed) ----------------
__device__ float g_a1[64*96*55*55];    // conv1 out
__device__ float g_p1[64*96*27*27];    // pool1 out
__device__ float g_a2[64*256*27*27];   // conv2 out
__device__ float g_p2[64*256*13*13];   // pool2 out
__device__ float g_a3[64*384*13*13];   // conv3 out
__device__ float g_a4[64*384*13*13];   // conv4 out
__device__ float g_a5[64*256*13*13];   // conv5 out
__device__ float g_p3[64*256*6*6];     // pool3 out -> flatten [64,9216]
__device__ float g_f1[64*4096];
__device__ float g_f2[64*4096];
__device__ float g_part[4*64*4096];    // FC k-split partials

// ---------------- conv1: 227x227x3 -> 55x55x96, k11 s4, (y+b+1)^2 ----------------
__global__ __launch_bounds__(128) void conv1_kernel(
    const float* __restrict__ x, const float* __restrict__ w,
    const float* __restrict__ b, float* __restrict__ y)
{
    const int co = blockIdx.y;   // 96
    const int n  = blockIdx.z;   // 64
    __shared__ float sw[3*11*11];
    for (int i = threadIdx.x; i < 363; i += blockDim.x) sw[i] = w[co*363 + i];
    __syncthreads();

    int tile = blockIdx.x * blockDim.x + threadIdx.x;   // 55 rows * 11 tiles
    if (tile >= 55*11) return;
    const int oh  = tile / 11;
    const int ow0 = (tile % 11) * 5;

    float acc[5] = {0.f,0.f,0.f,0.f,0.f};
    const float* xn = x + (size_t)n * (3*227*227);

    for (int c = 0; c < 3; ++c) {
        for (int kh = 0; kh < 11; ++kh) {
            const int ih = oh*4 + kh;
            const float* xrow = xn + ((size_t)c*227 + ih)*227 + ow0*4;
            float xv[27];
            #pragma unroll
            for (int i = 0; i < 27; ++i) xv[i] = xrow[i];
            const float* wr = &sw[(c*11 + kh)*11];
            #pragma unroll
            for (int kw = 0; kw < 11; ++kw) {
                const float wv = wr[kw];
                #pragma unroll
                for (int t = 0; t < 5; ++t) acc[t] += wv * xv[t*4 + kw];
            }
        }
    }
    const float vb = b[co] + 1.0f;
    float* yp = y + (((size_t)n*96 + co)*55 + oh)*55 + ow0;
    #pragma unroll
    for (int t = 0; t < 5; ++t) { float v = acc[t] + vb; yp[t] = v*v; }
}

// ---------------- stride-1 conv, square activation; one thread = one output row ----------------
template<int CIN, int K, int PAD, int HW, int BY>
__global__ __launch_bounds__(HW*BY) void conv_s1_sq(
    const float* __restrict__ x, const float* __restrict__ w,
    const float* __restrict__ b, float* __restrict__ y, int COUT)
{
    const int co = blockIdx.y;
    const int n  = blockIdx.x * BY + threadIdx.y;
    const int oh = threadIdx.x;

    __shared__ float sw[CIN*K*K];
    const int tid = threadIdx.y*HW + threadIdx.x;
    for (int i = tid; i < CIN*K*K; i += HW*BY) sw[i] = w[(size_t)co*CIN*K*K + i];
    __syncthreads();

    float acc[HW];
    #pragma unroll
    for (int t = 0; t < HW; ++t) acc[t] = 0.f;

    const float* xn = x + (size_t)n * CIN * HW * HW;
    for (int c = 0; c < CIN; ++c) {
        #pragma unroll
        for (int kh = 0; kh < K; ++kh) {
            const int ih = oh + kh - PAD;
            if (ih < 0 || ih >= HW) continue;
            const float* xrow = xn + ((size_t)c*HW + ih)*HW;
            float xv[HW + K - 1];
            #pragma unroll
            for (int i = 0; i < HW + K - 1; ++i) {
                const int iw = i - PAD;
                xv[i] = (iw >= 0 && iw < HW) ? xrow[iw] : 0.f;
            }
            const float* wr = &sw[(c*K + kh)*K];
            #pragma unroll
            for (int kw = 0; kw < K; ++kw) {
                const float wv = wr[kw];
                #pragma unroll
                for (int t = 0; t < HW; ++t) acc[t] += wv * xv[t + kw];
            }
        }
    }
    const float vb = b[co] + 1.0f;
    float* yp = y + ((((size_t)n*COUT + co)*HW) + oh) * HW;
    #pragma unroll
    for (int t = 0; t < HW; ++t) { float v = acc[t] + vb; yp[t] = v*v; }
}

// ---------------- 3x3 s2 avg pool ----------------
__global__ void avgpool_kernel(const float* __restrict__ x, float* __restrict__ y,
                               int H, int OH, int total)
{
    int idx = blockIdx.x*blockDim.x + threadIdx.x;
    if (idx >= total) return;
    int ow = idx % OH; int t = idx / OH;
    int oh = t % OH;   t /= OH;            // t = n*C + c
    const float* xp = x + ((size_t)t*H + oh*2)*H + ow*2;
    float s = 0.f;
    #pragma unroll
    for (int i = 0; i < 3; ++i)
        #pragma unroll
        for (int j = 0; j < 3; ++j) s += xp[i*H + j];
    y[idx] = s * (1.0f/9.0f);
}

// ---------------- FC: partial over K-split, M-split; part[s][m][n] ----------------
template<int MROWS>
__global__ __launch_bounds__(128) void fc_partial(
    const float* __restrict__ x, const float* __restrict__ w,
    float* __restrict__ part, int K, int N, int S)
{
    const int n  = blockIdx.x*128 + threadIdx.x;
    const int m0 = blockIdx.y * MROWS;
    const int s  = blockIdx.z;
    const int kc = K / S;          // K always divisible by S*32 here
    const int k0 = s*kc, k1 = k0 + kc;

    __shared__ float xs[MROWS][32];
    float acc[MROWS];
    #pragma unroll
    for (int i = 0; i < MROWS; ++i) acc[i] = 0.f;

    for (int kt = k0; kt < k1; kt += 32) {
        __syncthreads();
        for (int i = threadIdx.x; i < MROWS*32; i += 128) {
            int mm = i >> 5, kk = i & 31;
            xs[mm][kk] = x[(size_t)(m0+mm)*K + kt + kk];
        }
        __syncthreads();
        if (n < N) {
            #pragma unroll
            for (int kk = 0; kk < 32; kk += 4) {
                const float w0 = w[(size_t)(kt+kk  )*N + n];
                const float w1 = w[(size_t)(kt+kk+1)*N + n];
                const float w2 = w[(size_t)(kt+kk+2)*N + n];
                const float w3 = w[(size_t)(kt+kk+3)*N + n];
                #pragma unroll
                for (int mm = 0; mm < MROWS; ++mm) {
                    const float4 xv = *reinterpret_cast<const float4*>(&xs[mm][kk]);
                    acc[mm] += xv.x*w0 + xv.y*w1 + xv.z*w2 + xv.w*w3;
                }
            }
        }
    }
    if (n < N) {
        #pragma unroll
        for (int mm = 0; mm < MROWS; ++mm)
            part[((size_t)s*64 + m0 + mm)*N + n] = acc[mm];
    }
}

__global__ void fc_reduce(const float* __restrict__ part, const float* __restrict__ bias,
                          float* __restrict__ out, int N, int S, int total)
{
    int idx = blockIdx.x*blockDim.x + threadIdx.x;
    if (idx >= total) return;
    int n = idx % N;
    float s = bias[n];
    for (int i = 0; i < S; ++i) s += part[(size_t)i*64*N + idx];
    out[idx] = s;
}

// ---------------- host launcher ----------------
extern "C" void kernel_launch(void* const* d_in, const int* in_sizes, int n_in,
                              void* d_out, int out_size)
{
    const float* x   = (const float*)d_in[0];
    const float* w1  = (const float*)d_in[1];
    const float* b1  = (const float*)d_in[2];
    const float* w2  = (const float*)d_in[3];
    const float* b2  = (const float*)d_in[4];
    const float* w3  = (const float*)d_in[5];
    const float* b3  = (const float*)d_in[6];
    const float* w4  = (const float*)d_in[7];
    const float* b4  = (const float*)d_in[8];
    const float* w5  = (const float*)d_in[9];
    const float* b5  = (const float*)d_in[10];
    const float* fw1 = (const float*)d_in[11];
    const float* fb1 = (const float*)d_in[12];
    const float* fw2 = (const float*)d_in[13];
    const float* fb2 = (const float*)d_in[14];
    const float* fw3 = (const float*)d_in[15];
    const float* fb3 = (const float*)d_in[16];
    float* out = (float*)d_out;

    float *a1,*p1,*a2,*p2,*a3,*a4,*a5,*p3,*f1,*f2,*part;
    cudaGetSymbolAddress((void**)&a1, g_a1);
    cudaGetSymbolAddress((void**)&p1, g_p1);
    cudaGetSymbolAddress((void**)&a2, g_a2);
    cudaGetSymbolAddress((void**)&p2, g_p2);
    cudaGetSymbolAddress((void**)&a3, g_a3);
    cudaGetSymbolAddress((void**)&a4, g_a4);
    cudaGetSymbolAddress((void**)&a5, g_a5);
    cudaGetSymbolAddress((void**)&p3, g_p3);
    cudaGetSymbolAddress((void**)&f1, g_f1);
    cudaGetSymbolAddress((void**)&f2, g_f2);
    cudaGetSymbolAddress((void**)&part, g_part);

    // conv1 + square
    conv1_kernel<<<dim3(5, 96, 64), 128>>>(x, w1, b1, a1);
    // pool1: 55 -> 27
    {
        int total = 64*96*27*27;
        avgpool_kernel<<<(total + 255)/256, 256>>>(a1, p1, 55, 27, total);
    }
    // conv2 + square (96->256, k5 p2, 27x27)
    conv_s1_sq<96,5,2,27,4><<<dim3(16, 256), dim3(27, 4)>>>(p1, w2, b2, a2, 256);
    // pool2: 27 -> 13
    {
        int total = 64*256*13*13;
        avgpool_kernel<<<(total + 255)/256, 256>>>(a2, p2, 27, 13, total);
    }
    // conv3/4/5 + square (k3 p1, 13x13)
    conv_s1_sq<256,3,1,13,8><<<dim3(8, 384), dim3(13, 8)>>>(p2, w3, b3, a3, 384);
    conv_s1_sq<384,3,1,13,8><<<dim3(8, 384), dim3(13, 8)>>>(a3, w4, b4, a4, 384);
    conv_s1_sq<384,3,1,13,8><<<dim3(8, 256), dim3(13, 8)>>>(a4, w5, b5, a5, 256);
    // pool3: 13 -> 6  (flatten: contiguous NCHW)
    {
        int total = 64*256*6*6;
        avgpool_kernel<<<(total + 255)/256, 256>>>(a5, p3, 13, 6, total);
    }
    // fc1: [64,9216] x [9216,4096]
    fc_partial<16><<<dim3(32, 4, 4), 128>>>(p3, fw1, part, 9216, 4096, 4);
    fc_reduce<<<(64*4096 + 255)/256, 256>>>(part, fb1, f1, 4096, 4, 64*4096);
    // fc2: [64,4096] x [4096,4096]
    fc_partial<16><<<dim3(32, 4, 4), 128>>>(f1, fw2, part, 4096, 4096, 4);
    fc_reduce<<<(64*4096 + 255)/256, 256>>>(part, fb2, f2, 4096, 4, 64*4096);
    // fc3: [64,4096] x [4096,1000]
    fc_partial<16><<<dim3(8, 4, 4), 128>>>(f2, fw3, part, 4096, 1000, 4);
    fc_reduce<<<(64*1000 + 255)/256, 256>>>(part, fb3, out, 1000, 4, 64*1000);
}

// round 2
// speedup vs baseline: 3.1223x; 3.1223x over previous
#include <cuda_runtime.h>
#include <cuda_bf16.h>
#include <cstddef>

// ---------------- scratch (no cudaMalloc allowed) ----------------
__device__ float g_a1[64*96*55*55];    // conv1 out
__device__ float g_p1[64*96*27*27];    // pool1 out
__device__ float g_a2[64*256*27*27];   // conv2 out
__device__ float g_p2[64*256*13*13];   // pool2 out
__device__ float g_a3[64*384*13*13];   // conv3 out
__device__ float g_a4[64*384*13*13];   // conv4 out
__device__ float g_a5[64*256*13*13];   // conv5 out
__device__ float g_p3[64*256*6*6];     // pool3 out -> flatten [64,9216]
__device__ float g_f1[64*4096];
__device__ float g_f2[64*4096];
__device__ float g_part[4*64*4096];    // FC k-split partials

// ---------------- f32x2 helpers ----------------
__device__ __forceinline__ void fma2(unsigned long long &acc, unsigned long long a, unsigned long long b) {
    asm("fma.rn.f32x2 %0, %1, %2, %0;" : "+l"(acc) : "l"(a), "l"(b));
}
__device__ __forceinline__ unsigned long long pk2(float lo, float hi) {
    unsigned long long r;
    asm("mov.b64 %0, {%1, %2};" : "=l"(r) : "f"(lo), "f"(hi));
    return r;
}
__device__ __forceinline__ void upk2(float &lo, float &hi, unsigned long long v) {
    asm("mov.b64 {%0, %1}, %2;" : "=f"(lo), "=f"(hi) : "l"(v));
}

// ================= conv1: 3x227x227 -> 96x55x55, k11 s4, (y+b+1)^2 =================
// grid (28 oh-pairs, 3 co-groups of 32, 64 n), block (28 tx, 4 ty)
// thread: 8 co x 2 oh x 2 ow (ow = tx, tx+28). Phase-split shared x for stride-4.
__global__ __launch_bounds__(112) void conv1_v2(
    const float* __restrict__ x, const float* __restrict__ w,
    const float* __restrict__ b, float* __restrict__ y)
{
    __shared__ __align__(16) float xs[4][15][58];   // [phase][row][p], iw = 4p+phase
    __shared__ __align__(16) float ws[32][121];

    const int tx = threadIdx.x;            // 0..27
    const int ty = threadIdx.y;            // 0..3  -> co = co0 + ty*8 + cc
    const int tid = ty*28 + tx;            // 0..111
    const int blk = blockIdx.x;            // oh pair
    const int co0 = blockIdx.y * 32;
    const int n   = blockIdx.z;
    const int ih0 = blk * 8;

    // zero xs once (covers never-written border cells)
    for (int i = tid; i < 4*15*58; i += 112) ((float*)xs)[i] = 0.f;

    float acc[2][2][8];
    #pragma unroll
    for (int o = 0; o < 2; ++o)
        #pragma unroll
        for (int j = 0; j < 2; ++j)
            #pragma unroll
            for (int cc = 0; cc < 8; ++cc) acc[o][j][cc] = 0.f;

    const float* xn = x + (size_t)n * (3*227*227);

    for (int c = 0; c < 3; ++c) {
        __syncthreads();
        for (int i = tid; i < 32*121; i += 112) {
            int ci = i / 121, k = i % 121;
            ws[ci][k] = w[(size_t)(co0+ci)*363 + c*121 + k];
        }
        for (int i = tid; i < 15*227; i += 112) {
            int r = i / 227, iw = i % 227;
            int ih = ih0 + r;
            xs[iw & 3][r][iw >> 2] = (ih < 227) ? xn[((size_t)c*227 + ih)*227 + iw] : 0.f;
        }
        __syncthreads();

        #pragma unroll
        for (int kh = 0; kh < 11; ++kh) {
            #pragma unroll
            for (int kw = 0; kw < 11; ++kw) {
                const int kr = kw & 3, kq = kw >> 2;
                const float x00 = xs[kr][kh][tx + kq];
                const float x01 = xs[kr][kh][tx + 28 + kq];
                const float x10 = xs[kr][kh + 4][tx + kq];
                const float x11 = xs[kr][kh + 4][tx + 28 + kq];
                #pragma unroll
                for (int cc = 0; cc < 8; ++cc) {
                    const float wv = ws[ty*8 + cc][kh*11 + kw];
                    acc[0][0][cc] += wv * x00;
                    acc[0][1][cc] += wv * x01;
                    acc[1][0][cc] += wv * x10;
                    acc[1][1][cc] += wv * x11;
                }
            }
        }
    }

    #pragma unroll
    for (int cc = 0; cc < 8; ++cc) {
        const int co = co0 + ty*8 + cc;
        const float vb = b[co] + 1.0f;
        #pragma unroll
        for (int o = 0; o < 2; ++o) {
            const int oh = blk*2 + o;
            if (oh >= 55) continue;
            #pragma unroll
            for (int j = 0; j < 2; ++j) {
                const int ow = tx + 28*j;
                if (ow >= 55) continue;
                float v = acc[o][j][cc] + vb;
                y[(((size_t)n*96 + co)*55 + oh)*55 + ow] = v*v;
            }
        }
    }
}

// ================= conv2: 96x27x27 -> 256x27x27, k5 p2, (y+b+1)^2 =================
// grid (3 ohblk, 8 cogrp, 64 n), block (7 owg, 9 ohl, 4 cog)
// thread: 8 co (4 f32x2 pairs) x 4 ow (ow = owg+7j) x 1 oh.
__global__ __launch_bounds__(252) void conv2_v2(
    const float* __restrict__ x, const float* __restrict__ w,
    const float* __restrict__ b, float* __restrict__ y)
{
    __shared__ __align__(16) float xs[4][13][37];   // [cin_l][row][p], p = iw+2
    __shared__ __align__(16) float ws[4][25][32];   // [cin_l][k][co_l]

    const int owg = threadIdx.x;      // 0..6
    const int ty  = threadIdx.y;      // 0..8 (oh local)
    const int tz  = threadIdx.z;      // 0..3 (co group of 8)
    const int tid = (tz*9 + ty)*7 + owg;
    const int ohblk = blockIdx.x;     // 0..2
    const int co0g  = blockIdx.y * 32;
    const int n     = blockIdx.z;
    const int oh    = ohblk*9 + ty;

    for (int i = tid; i < 4*13*37; i += 252) ((float*)xs)[i] = 0.f;

    unsigned long long acc2[4][4];    // [j][pair]
    #pragma unroll
    for (int j = 0; j < 4; ++j)
        #pragma unroll
        for (int p = 0; p < 4; ++p) acc2[j][p] = 0ull;

    const float* xn = x + (size_t)n * (96*27*27);

    for (int ci0 = 0; ci0 < 96; ci0 += 4) {
        __syncthreads();
        // stage x (4 cin planes)
        for (int i = tid; i < 4*13*27; i += 252) {
            int cl = i / 351, s = i % 351;
            int r = s / 27, iw = s % 27;
            int ih = ohblk*9 - 2 + r;
            if (ih >= 0 && ih < 27)
                xs[cl][r][iw + 2] = xn[((size_t)(ci0+cl)*27 + ih)*27 + iw];
        }
        // stage w (coalesced in 100-float runs)
        for (int i = tid; i < 3200; i += 252) {
            int ci = i / 100, r = i % 100;
            int cl = r / 25, k = r % 25;
            ws[cl][k][ci] = w[(size_t)(co0g+ci)*2400 + (ci0+cl)*25 + k];
        }
        __syncthreads();

        #pragma unroll
        for (int cl = 0; cl < 4; ++cl) {
            #pragma unroll
            for (int kh = 0; kh < 5; ++kh) {
                const int r = ty + kh;
                float xv[4][5];
                #pragma unroll
                for (int j = 0; j < 4; ++j)
                    #pragma unroll
                    for (int dk = 0; dk < 5; ++dk)
                        xv[j][dk] = xs[cl][r][owg + 7*j + dk];
                #pragma unroll
                for (int kw = 0; kw < 5; ++kw) {
                    unsigned long long w2[4];
                    #pragma unroll
                    for (int p = 0; p < 4; ++p)
                        w2[p] = *reinterpret_cast<const unsigned long long*>(&ws[cl][kh*5 + kw][tz*8 + 2*p]);
                    #pragma unroll
                    for (int j = 0; j < 4; ++j) {
                        const unsigned long long xp = pk2(xv[j][kw], xv[j][kw]);
                        #pragma unroll
                        for (int p = 0; p < 4; ++p) fma2(acc2[j][p], xp, w2[p]);
                    }
                }
            }
        }
    }

    #pragma unroll
    for (int p = 0; p < 4; ++p) {
        const int coA = co0g + tz*8 + 2*p;
        const float vbA = b[coA] + 1.0f;
        const float vbB = b[coA+1] + 1.0f;
        #pragma unroll
        for (int j = 0; j < 4; ++j) {
            const int ow = owg + 7*j;
            if (ow >= 27) continue;
            float v0, v1;
            upk2(v0, v1, acc2[j][p]);
            v0 += vbA; v1 += vbB;
            y[(((size_t)n*256 + coA  )*27 + oh)*27 + ow] = v0*v0;
            y[(((size_t)n*256 + coA+1)*27 + oh)*27 + ow] = v1*v1;
        }
    }
}

// ================= conv3/4/5: CINx13x13 -> COUTx13x13, k3 p1, (y+b+1)^2 =================
// grid (COUT/32, 64 n), block (13 oh, 16 cog); thread: 2 co x full 13-ow row (7 f32x2 pairs)
template<int CIN>
__global__ __launch_bounds__(208) void conv3_v2(
    const float* __restrict__ x, const float* __restrict__ w,
    const float* __restrict__ b, float* __restrict__ y, int COUT)
{
    __shared__ __align__(16) float xs[8][15][17];   // [cin_l][row=ih+1][p=iw+1]
    __shared__ __align__(16) float ws[8][9][32];    // [cin_l][k][co_l]

    const int ty  = threadIdx.x;      // 0..12 (oh)
    const int tz  = threadIdx.y;      // 0..15 (co pair group)
    const int tid = tz*13 + ty;
    const int co0g = blockIdx.x * 32;
    const int n    = blockIdx.y;

    for (int i = tid; i < 8*15*17; i += 208) ((float*)xs)[i] = 0.f;

    unsigned long long acc2[2][7];
    #pragma unroll
    for (int cc = 0; cc < 2; ++cc)
        #pragma unroll
        for (int i = 0; i < 7; ++i) acc2[cc][i] = 0ull;

    const float* xn = x + (size_t)n * CIN * 169;

    for (int ci0 = 0; ci0 < CIN; ci0 += 8) {
        __syncthreads();
        for (int i = tid; i < 8*169; i += 208) {
            int cl = i / 169, s = i % 169;
            int ih = s / 13, iw = s % 13;
            xs[cl][ih + 1][iw + 1] = xn[((size_t)(ci0+cl)*13 + ih)*13 + iw];
        }
        for (int i = tid; i < 8*9*32; i += 208) {
            int ci = i / 72, r = i % 72;
            int cl = r / 9, k = r % 9;
            ws[cl][k][ci] = w[(size_t)(co0g+ci)*CIN*9 + (ci0+cl)*9 + k];
        }
        __syncthreads();

        #pragma unroll
        for (int cl = 0; cl < 8; ++cl) {
            #pragma unroll
            for (int kh = 0; kh < 3; ++kh) {
                const int row = ty + kh;
                float xv[16];
                #pragma unroll
                for (int p = 0; p < 16; ++p) xv[p] = xs[cl][row][p];
                unsigned long long E[8], O[7];
                #pragma unroll
                for (int i = 0; i < 8; ++i) E[i] = pk2(xv[2*i], xv[2*i+1]);
                #pragma unroll
                for (int i = 0; i < 7; ++i) O[i] = pk2(xv[2*i+1], xv[2*i+2]);
                #pragma unroll
                for (int cc = 0; cc < 2; ++cc) {
                    const int col = tz*2 + cc;
                    const unsigned long long w0 = pk2(ws[cl][kh*3+0][col], ws[cl][kh*3+0][col]);
                    const unsigned long long w1 = pk2(ws[cl][kh*3+1][col], ws[cl][kh*3+1][col]);
                    const unsigned long long w2v = pk2(ws[cl][kh*3+2][col], ws[cl][kh*3+2][col]);
                    #pragma unroll
                    for (int i = 0; i < 7; ++i) {
                        fma2(acc2[cc][i], E[i],   w0);
                        fma2(acc2[cc][i], O[i],   w1);
                        fma2(acc2[cc][i], E[i+1], w2v);
                    }
                }
            }
        }
    }

    #pragma unroll
    for (int cc = 0; cc < 2; ++cc) {
        const int co = co0g + tz*2 + cc;
        const float vb = b[co] + 1.0f;
        float* yp = y + (((size_t)n*COUT + co)*13 + ty)*13;
        #pragma unroll
        for (int i = 0; i < 7; ++i) {
            float v0, v1;
            upk2(v0, v1, acc2[cc][i]);
            v0 += vb; yp[2*i] = v0*v0;
            if (2*i + 1 < 13) { v1 += vb; yp[2*i+1] = v1*v1; }
        }
    }
}

// ---------------- 3x3 s2 avg pool ----------------
__global__ void avgpool_kernel(const float* __restrict__ x, float* __restrict__ y,
                               int H, int OH, int total)
{
    int idx = blockIdx.x*blockDim.x + threadIdx.x;
    if (idx >= total) return;
    int ow = idx % OH; int t = idx / OH;
    int oh = t % OH;   t /= OH;            // t = n*C + c
    const float* xp = x + ((size_t)t*H + oh*2)*H + ow*2;
    float s = 0.f;
    #pragma unroll
    for (int i = 0; i < 3; ++i)
        #pragma unroll
        for (int j = 0; j < 3; ++j) s += xp[i*H + j];
    y[idx] = s * (1.0f/9.0f);
}

// ---------------- FC: partial over K-split, M-split; part[s][m][n] ----------------
template<int MROWS>
__global__ __launch_bounds__(128) void fc_partial(
    const float* __restrict__ x, const float* __restrict__ w,
    float* __restrict__ part, int K, int N, int S)
{
    const int n  = blockIdx.x*128 + threadIdx.x;
    const int m0 = blockIdx.y * MROWS;
    const int s  = blockIdx.z;
    const int kc = K / S;
    const int k0 = s*kc, k1 = k0 + kc;

    __shared__ float xs[MROWS][32];
    float acc[MROWS];
    #pragma unroll
    for (int i = 0; i < MROWS; ++i) acc[i] = 0.f;

    for (int kt = k0; kt < k1; kt += 32) {
        __syncthreads();
        for (int i = threadIdx.x; i < MROWS*32; i += 128) {
            int mm = i >> 5, kk = i & 31;
            xs[mm][kk] = x[(size_t)(m0+mm)*K + kt + kk];
        }
        __syncthreads();
        if (n < N) {
            #pragma unroll
            for (int kk = 0; kk < 32; kk += 4) {
                const float w0 = w[(size_t)(kt+kk  )*N + n];
                const float w1 = w[(size_t)(kt+kk+1)*N + n];
                const float w2 = w[(size_t)(kt+kk+2)*N + n];
                const float w3 = w[(size_t)(kt+kk+3)*N + n];
                #pragma unroll
                for (int mm = 0; mm < MROWS; ++mm) {
                    const float4 xv = *reinterpret_cast<const float4*>(&xs[mm][kk]);
                    acc[mm] += xv.x*w0 + xv.y*w1 + xv.z*w2 + xv.w*w3;
                }
            }
        }
    }
    if (n < N) {
        #pragma unroll
        for (int mm = 0; mm < MROWS; ++mm)
            part[((size_t)s*64 + m0 + mm)*N + n] = acc[mm];
    }
}

__global__ void fc_reduce(const float* __restrict__ part, const float* __restrict__ bias,
                          float* __restrict__ out, int N, int S, int total)
{
    int idx = blockIdx.x*blockDim.x + threadIdx.x;
    if (idx >= total) return;
    int n = idx % N;
    float s = bias[n];
    for (int i = 0; i < S; ++i) s += part[(size_t)i*64*N + idx];
    out[idx] = s;
}

// ---------------- host launcher ----------------
extern "C" void kernel_launch(void* const* d_in, const int* in_sizes, int n_in,
                              void* d_out, int out_size)
{
    const float* x   = (const float*)d_in[0];
    const float* w1  = (const float*)d_in[1];
    const float* b1  = (const float*)d_in[2];
    const float* w2  = (const float*)d_in[3];
    const float* b2  = (const float*)d_in[4];
    const float* w3  = (const float*)d_in[5];
    const float* b3  = (const float*)d_in[6];
    const float* w4  = (const float*)d_in[7];
    const float* b4  = (const float*)d_in[8];
    const float* w5  = (const float*)d_in[9];
    const float* b5  = (const float*)d_in[10];
    const float* fw1 = (const float*)d_in[11];
    const float* fb1 = (const float*)d_in[12];
    const float* fw2 = (const float*)d_in[13];
    const float* fb2 = (const float*)d_in[14];
    const float* fw3 = (const float*)d_in[15];
    const float* fb3 = (const float*)d_in[16];
    float* out = (float*)d_out;

    float *a1,*p1,*a2,*p2,*a3,*a4,*a5,*p3,*f1,*f2,*part;
    cudaGetSymbolAddress((void**)&a1, g_a1);
    cudaGetSymbolAddress((void**)&p1, g_p1);
    cudaGetSymbolAddress((void**)&a2, g_a2);
    cudaGetSymbolAddress((void**)&p2, g_p2);
    cudaGetSymbolAddress((void**)&a3, g_a3);
    cudaGetSymbolAddress((void**)&a4, g_a4);
    cudaGetSymbolAddress((void**)&a5, g_a5);
    cudaGetSymbolAddress((void**)&p3, g_p3);
    cudaGetSymbolAddress((void**)&f1, g_f1);
    cudaGetSymbolAddress((void**)&f2, g_f2);
    cudaGetSymbolAddress((void**)&part, g_part);

    // conv1 + square
    conv1_v2<<<dim3(28, 3, 64), dim3(28, 4)>>>(x, w1, b1, a1);
    // pool1: 55 -> 27
    {
        int total = 64*96*27*27;
        avgpool_kernel<<<(total + 255)/256, 256>>>(a1, p1, 55, 27, total);
    }
    // conv2 + square
    conv2_v2<<<dim3(3, 8, 64), dim3(7, 9, 4)>>>(p1, w2, b2, a2);
    // pool2: 27 -> 13
    {
        int total = 64*256*13*13;
        avgpool_kernel<<<(total + 255)/256, 256>>>(a2, p2, 27, 13, total);
    }
    // conv3/4/5 + square
    conv3_v2<256><<<dim3(12, 64), dim3(13, 16)>>>(p2, w3, b3, a3, 384);
    conv3_v2<384><<<dim3(12, 64), dim3(13, 16)>>>(a3, w4, b4, a4, 384);
    conv3_v2<384><<<dim3(8, 64),  dim3(13, 16)>>>(a4, w5, b5, a5, 256);
    // pool3: 13 -> 6
    {
        int total = 64*256*6*6;
        avgpool_kernel<<<(total + 255)/256, 256>>>(a5, p3, 13, 6, total);
    }
    // fc1: [64,9216] x [9216,4096]
    fc_partial<16><<<dim3(32, 4, 4), 128>>>(p3, fw1, part, 9216, 4096, 4);
    fc_reduce<<<(64*4096 + 255)/256, 256>>>(part, fb1, f1, 4096, 4, 64*4096);
    // fc2: [64,4096] x [4096,4096]
    fc_partial<16><<<dim3(32, 4, 4), 128>>>(f1, fw2, part, 4096, 4096, 4);
    fc_reduce<<<(64*4096 + 255)/256, 256>>>(part, fb2, f2, 4096, 4, 64*4096);
    // fc3: [64,4096] x [4096,1000]
    fc_partial<16><<<dim3(8, 4, 4), 128>>>(f2, fw3, part, 4096, 1000, 4);
    fc_reduce<<<(64*1000 + 255)/256, 256>>>(part, fb3, out, 1000, 4, 64*1000);
}

// round 3
// speedup vs baseline: 3.1419x; 1.0063x over previous
#include <cuda_runtime.h>
#include <cuda_bf16.h>
#include <cstddef>

// ---------------- scratch (no cudaMalloc allowed) ----------------
__device__ float g_a1[64*96*55*55];    // conv1 out
__device__ float g_p1[64*96*27*27];    // pool1 out
__device__ float g_a2[64*256*27*27];   // conv2 out
__device__ float g_p2[64*256*13*13];   // pool2 out
__device__ float g_a3[64*384*13*13];   // conv3 out
__device__ float g_a4[64*384*13*13];   // conv4 out
__device__ float g_a5[64*256*13*13];   // conv5 out
__device__ float g_p3[64*256*6*6];     // pool3 out -> flatten [64,9216]
__device__ float g_f1[64*4096];
__device__ float g_f2[64*4096];
__device__ float g_part[4*64*4096];    // FC k-split partials

// ---------------- f32x2 helpers ----------------
__device__ __forceinline__ void fma2(unsigned long long &acc, unsigned long long a, unsigned long long b) {
    asm("fma.rn.f32x2 %0, %1, %2, %0;" : "+l"(acc) : "l"(a), "l"(b));
}
__device__ __forceinline__ unsigned long long pk2(float lo, float hi) {
    unsigned long long r;
    asm("mov.b64 %0, {%1, %2};" : "=l"(r) : "f"(lo), "f"(hi));
    return r;
}
__device__ __forceinline__ void upk2(float &lo, float &hi, unsigned long long v) {
    asm("mov.b64 {%0, %1}, %2;" : "=f"(lo), "=f"(hi) : "l"(v));
}

// ================= conv1: 3x227x227 -> 96x55x55, k11 s4, (y+b+1)^2 =================
// grid (28 oh-pairs, 3 co-groups of 32, 64 n), block (28 tx, 4 ty)
// thread: 8 co x 2 oh x 2 ow (ow = tx, tx+28). Phase-split shared x for stride-4.
__global__ __launch_bounds__(112) void conv1_v2(
    const float* __restrict__ x, const float* __restrict__ w,
    const float* __restrict__ b, float* __restrict__ y)
{
    __shared__ __align__(16) float xs[4][15][58];   // [phase][row][p], iw = 4p+phase
    __shared__ __align__(16) float ws[32][121];

    const int tx = threadIdx.x;            // 0..27
    const int ty = threadIdx.y;            // 0..3  -> co = co0 + ty*8 + cc
    const int tid = ty*28 + tx;            // 0..111
    const int blk = blockIdx.x;            // oh pair
    const int co0 = blockIdx.y * 32;
    const int n   = blockIdx.z;
    const int ih0 = blk * 8;

    // zero xs once (covers never-written border cells)
    for (int i = tid; i < 4*15*58; i += 112) ((float*)xs)[i] = 0.f;

    float acc[2][2][8];
    #pragma unroll
    for (int o = 0; o < 2; ++o)
        #pragma unroll
        for (int j = 0; j < 2; ++j)
            #pragma unroll
            for (int cc = 0; cc < 8; ++cc) acc[o][j][cc] = 0.f;

    const float* xn = x + (size_t)n * (3*227*227);

    for (int c = 0; c < 3; ++c) {
        __syncthreads();
        for (int i = tid; i < 32*121; i += 112) {
            int ci = i / 121, k = i % 121;
            ws[ci][k] = w[(size_t)(co0+ci)*363 + c*121 + k];
        }
        for (int i = tid; i < 15*227; i += 112) {
            int r = i / 227, iw = i % 227;
            int ih = ih0 + r;
            xs[iw & 3][r][iw >> 2] = (ih < 227) ? xn[((size_t)c*227 + ih)*227 + iw] : 0.f;
        }
        __syncthreads();

        #pragma unroll
        for (int kh = 0; kh < 11; ++kh) {
            #pragma unroll
            for (int kw = 0; kw < 11; ++kw) {
                const int kr = kw & 3, kq = kw >> 2;
                const float x00 = xs[kr][kh][tx + kq];
                const float x01 = xs[kr][kh][tx + 28 + kq];
                const float x10 = xs[kr][kh + 4][tx + kq];
                const float x11 = xs[kr][kh + 4][tx + 28 + kq];
                #pragma unroll
                for (int cc = 0; cc < 8; ++cc) {
                    const float wv = ws[ty*8 + cc][kh*11 + kw];
                    acc[0][0][cc] += wv * x00;
                    acc[0][1][cc] += wv * x01;
                    acc[1][0][cc] += wv * x10;
                    acc[1][1][cc] += wv * x11;
                }
            }
        }
    }

    #pragma unroll
    for (int cc = 0; cc < 8; ++cc) {
        const int co = co0 + ty*8 + cc;
        const float vb = b[co] + 1.0f;
        #pragma unroll
        for (int o = 0; o < 2; ++o) {
            const int oh = blk*2 + o;
            if (oh >= 55) continue;
            #pragma unroll
            for (int j = 0; j < 2; ++j) {
                const int ow = tx + 28*j;
                if (ow >= 55) continue;
                float v = acc[o][j][cc] + vb;
                y[(((size_t)n*96 + co)*55 + oh)*55 + ow] = v*v;
            }
        }
    }
}

// ================= conv2: 96x27x27 -> 256x27x27, k5 p2, (y+b+1)^2 =================
// grid (3 ohblk, 8 cogrp, 64 n), block (7 owg, 9 ohl, 4 cog)
// thread: 8 co (4 f32x2 pairs) x 4 ow (ow = owg+7j) x 1 oh.
__global__ __launch_bounds__(252) void conv2_v2(
    const float* __restrict__ x, const float* __restrict__ w,
    const float* __restrict__ b, float* __restrict__ y)
{
    __shared__ __align__(16) float xs[4][13][37];   // [cin_l][row][p], p = iw+2
    __shared__ __align__(16) float ws[4][25][32];   // [cin_l][k][co_l]

    const int owg = threadIdx.x;      // 0..6
    const int ty  = threadIdx.y;      // 0..8 (oh local)
    const int tz  = threadIdx.z;      // 0..3 (co group of 8)
    const int tid = (tz*9 + ty)*7 + owg;
    const int ohblk = blockIdx.x;     // 0..2
    const int co0g  = blockIdx.y * 32;
    const int n     = blockIdx.z;
    const int oh    = ohblk*9 + ty;

    for (int i = tid; i < 4*13*37; i += 252) ((float*)xs)[i] = 0.f;

    unsigned long long acc2[4][4];    // [j][pair]
    #pragma unroll
    for (int j = 0; j < 4; ++j)
        #pragma unroll
        for (int p = 0; p < 4; ++p) acc2[j][p] = 0ull;

    const float* xn = x + (size_t)n * (96*27*27);

    for (int ci0 = 0; ci0 < 96; ci0 += 4) {
        __syncthreads();
        // stage x (4 cin planes)
        for (int i = tid; i < 4*13*27; i += 252) {
            int cl = i / 351, s = i % 351;
            int r = s / 27, iw = s % 27;
            int ih = ohblk*9 - 2 + r;
            if (ih >= 0 && ih < 27)
                xs[cl][r][iw + 2] = xn[((size_t)(ci0+cl)*27 + ih)*27 + iw];
        }
        // stage w (coalesced in 100-float runs)
        for (int i = tid; i < 3200; i += 252) {
            int ci = i / 100, r = i % 100;
            int cl = r / 25, k = r % 25;
            ws[cl][k][ci] = w[(size_t)(co0g+ci)*2400 + (ci0+cl)*25 + k];
        }
        __syncthreads();

        #pragma unroll
        for (int cl = 0; cl < 4; ++cl) {
            #pragma unroll
            for (int kh = 0; kh < 5; ++kh) {
                const int r = ty + kh;
                float xv[4][5];
                #pragma unroll
                for (int j = 0; j < 4; ++j)
                    #pragma unroll
                    for (int dk = 0; dk < 5; ++dk)
                        xv[j][dk] = xs[cl][r][owg + 7*j + dk];
                #pragma unroll
                for (int kw = 0; kw < 5; ++kw) {
                    unsigned long long w2[4];
                    #pragma unroll
                    for (int p = 0; p < 4; ++p)
                        w2[p] = *reinterpret_cast<const unsigned long long*>(&ws[cl][kh*5 + kw][tz*8 + 2*p]);
                    #pragma unroll
                    for (int j = 0; j < 4; ++j) {
                        const unsigned long long xp = pk2(xv[j][kw], xv[j][kw]);
                        #pragma unroll
                        for (int p = 0; p < 4; ++p) fma2(acc2[j][p], xp, w2[p]);
                    }
                }
            }
        }
    }

    #pragma unroll
    for (int p = 0; p < 4; ++p) {
        const int coA = co0g + tz*8 + 2*p;
        const float vbA = b[coA] + 1.0f;
        const float vbB = b[coA+1] + 1.0f;
        #pragma unroll
        for (int j = 0; j < 4; ++j) {
            const int ow = owg + 7*j;
            if (ow >= 27) continue;
            float v0, v1;
            upk2(v0, v1, acc2[j][p]);
            v0 += vbA; v1 += vbB;
            y[(((size_t)n*256 + coA  )*27 + oh)*27 + ow] = v0*v0;
            y[(((size_t)n*256 + coA+1)*27 + oh)*27 + ow] = v1*v1;
        }
    }
}

// ================= conv3/4/5: CINx13x13 -> COUTx13x13, k3 p1, (y+b+1)^2 =================
// grid (COUT/32, 64 n), block (13 oh, 16 cog); thread: 2 co x full 13-ow row (7 f32x2 pairs)
template<int CIN>
__global__ __launch_bounds__(208) void conv3_v2(
    const float* __restrict__ x, const float* __restrict__ w,
    const float* __restrict__ b, float* __restrict__ y, int COUT)
{
    __shared__ __align__(16) float xs[8][15][17];   // [cin_l][row=ih+1][p=iw+1]
    __shared__ __align__(16) float ws[8][9][32];    // [cin_l][k][co_l]

    const int ty  = threadIdx.x;      // 0..12 (oh)
    const int tz  = threadIdx.y;      // 0..15 (co pair group)
    const int tid = tz*13 + ty;
    const int co0g = blockIdx.x * 32;
    const int n    = blockIdx.y;

    for (int i = tid; i < 8*15*17; i += 208) ((float*)xs)[i] = 0.f;

    unsigned long long acc2[2][7];
    #pragma unroll
    for (int cc = 0; cc < 2; ++cc)
        #pragma unroll
        for (int i = 0; i < 7; ++i) acc2[cc][i] = 0ull;

    const float* xn = x + (size_t)n * CIN * 169;

    for (int ci0 = 0; ci0 < CIN; ci0 += 8) {
        __syncthreads();
        for (int i = tid; i < 8*169; i += 208) {
            int cl = i / 169, s = i % 169;
            int ih = s / 13, iw = s % 13;
            xs[cl][ih + 1][iw + 1] = xn[((size_t)(ci0+cl)*13 + ih)*13 + iw];
        }
        for (int i = tid; i < 8*9*32; i += 208) {
            int ci = i / 72, r = i % 72;
            int cl = r / 9, k = r % 9;
            ws[cl][k][ci] = w[(size_t)(co0g+ci)*CIN*9 + (ci0+cl)*9 + k];
        }
        __syncthreads();

        #pragma unroll
        for (int cl = 0; cl < 8; ++cl) {
            #pragma unroll
            for (int kh = 0; kh < 3; ++kh) {
                const int row = ty + kh;
                float xv[16];
                #pragma unroll
                for (int p = 0; p < 16; ++p) xv[p] = xs[cl][row][p];
                unsigned long long E[8], O[7];
                #pragma unroll
                for (int i = 0; i < 8; ++i) E[i] = pk2(xv[2*i], xv[2*i+1]);
                #pragma unroll
                for (int i = 0; i < 7; ++i) O[i] = pk2(xv[2*i+1], xv[2*i+2]);
                #pragma unroll
                for (int cc = 0; cc < 2; ++cc) {
                    const int col = tz*2 + cc;
                    const unsigned long long w0 = pk2(ws[cl][kh*3+0][col], ws[cl][kh*3+0][col]);
                    const unsigned long long w1 = pk2(ws[cl][kh*3+1][col], ws[cl][kh*3+1][col]);
                    const unsigned long long w2v = pk2(ws[cl][kh*3+2][col], ws[cl][kh*3+2][col]);
                    #pragma unroll
                    for (int i = 0; i < 7; ++i) {
                        fma2(acc2[cc][i], E[i],   w0);
                        fma2(acc2[cc][i], O[i],   w1);
                        fma2(acc2[cc][i], E[i+1], w2v);
                    }
                }
            }
        }
    }

    #pragma unroll
    for (int cc = 0; cc < 2; ++cc) {
        const int co = co0g + tz*2 + cc;
        const float vb = b[co] + 1.0f;
        float* yp = y + (((size_t)n*COUT + co)*13 + ty)*13;
        #pragma unroll
        for (int i = 0; i < 7; ++i) {
            float v0, v1;
            upk2(v0, v1, acc2[cc][i]);
            v0 += vb; yp[2*i] = v0*v0;
            if (2*i + 1 < 13) { v1 += vb; yp[2*i+1] = v1*v1; }
        }
    }
}

// ---------------- 3x3 s2 avg pool ----------------
__global__ void avgpool_kernel(const float* __restrict__ x, float* __restrict__ y,
                               int H, int OH, int total)
{
    int idx = blockIdx.x*blockDim.x + threadIdx.x;
    if (idx >= total) return;
    int ow = idx % OH; int t = idx / OH;
    int oh = t % OH;   t /= OH;            // t = n*C + c
    const float* xp = x + ((size_t)t*H + oh*2)*H + ow*2;
    float s = 0.f;
    #pragma unroll
    for (int i = 0; i < 3; ++i)
        #pragma unroll
        for (int j = 0; j < 3; ++j) s += xp[i*H + j];
    y[idx] = s * (1.0f/9.0f);
}

// ---------------- FC: partial over K-split, M-split; part[s][m][n] ----------------
template<int MROWS>
__global__ __launch_bounds__(128) void fc_partial(
    const float* __restrict__ x, const float* __restrict__ w,
    float* __restrict__ part, int K, int N, int S)
{
    const int n  = blockIdx.x*128 + threadIdx.x;
    const int m0 = blockIdx.y * MROWS;
    const int s  = blockIdx.z;
    const int kc = K / S;
    const int k0 = s*kc, k1 = k0 + kc;

    __shared__ float xs[MROWS][32];
    float acc[MROWS];
    #pragma unroll
    for (int i = 0; i < MROWS; ++i) acc[i] = 0.f;

    for (int kt = k0; kt < k1; kt += 32) {
        __syncthreads();
        for (int i = threadIdx.x; i < MROWS*32; i += 128) {
            int mm = i >> 5, kk = i & 31;
            xs[mm][kk] = x[(size_t)(m0+mm)*K + kt + kk];
        }
        __syncthreads();
        if (n < N) {
            #pragma unroll
            for (int kk = 0; kk < 32; kk += 4) {
                const float w0 = w[(size_t)(kt+kk  )*N + n];
                const float w1 = w[(size_t)(kt+kk+1)*N + n];
                const float w2 = w[(size_t)(kt+kk+2)*N + n];
                const float w3 = w[(size_t)(kt+kk+3)*N + n];
                #pragma unroll
                for (int mm = 0; mm < MROWS; ++mm) {
                    const float4 xv = *reinterpret_cast<const float4*>(&xs[mm][kk]);
                    acc[mm] += xv.x*w0 + xv.y*w1 + xv.z*w2 + xv.w*w3;
                }
            }
        }
    }
    if (n < N) {
        #pragma unroll
        for (int mm = 0; mm < MROWS; ++mm)
            part[((size_t)s*64 + m0 + mm)*N + n] = acc[mm];
    }
}

__global__ void fc_reduce(const float* __restrict__ part, const float* __restrict__ bias,
                          float* __restrict__ out, int N, int S, int total)
{
    int idx = blockIdx.x*blockDim.x + threadIdx.x;
    if (idx >= total) return;
    int n = idx % N;
    float s = bias[n];
    for (int i = 0; i < S; ++i) s += part[(size_t)i*64*N + idx];
    out[idx] = s;
}

// ---------------- host launcher ----------------
extern "C" void kernel_launch(void* const* d_in, const int* in_sizes, int n_in,
                              void* d_out, int out_size)
{
    const float* x   = (const float*)d_in[0];
    const float* w1  = (const float*)d_in[1];
    const float* b1  = (const float*)d_in[2];
    const float* w2  = (const float*)d_in[3];
    const float* b2  = (const float*)d_in[4];
    const float* w3  = (const float*)d_in[5];
    const float* b3  = (const float*)d_in[6];
    const float* w4  = (const float*)d_in[7];
    const float* b4  = (const float*)d_in[8];
    const float* w5  = (const float*)d_in[9];
    const float* b5  = (const float*)d_in[10];
    const float* fw1 = (const float*)d_in[11];
    const float* fb1 = (const float*)d_in[12];
    const float* fw2 = (const float*)d_in[13];
    const float* fb2 = (const float*)d_in[14];
    const float* fw3 = (const float*)d_in[15];
    const float* fb3 = (const float*)d_in[16];
    float* out = (float*)d_out;

    float *a1,*p1,*a2,*p2,*a3,*a4,*a5,*p3,*f1,*f2,*part;
    cudaGetSymbolAddress((void**)&a1, g_a1);
    cudaGetSymbolAddress((void**)&p1, g_p1);
    cudaGetSymbolAddress((void**)&a2, g_a2);
    cudaGetSymbolAddress((void**)&p2, g_p2);
    cudaGetSymbolAddress((void**)&a3, g_a3);
    cudaGetSymbolAddress((void**)&a4, g_a4);
    cudaGetSymbolAddress((void**)&a5, g_a5);
    cudaGetSymbolAddress((void**)&p3, g_p3);
    cudaGetSymbolAddress((void**)&f1, g_f1);
    cudaGetSymbolAddress((void**)&f2, g_f2);
    cudaGetSymbolAddress((void**)&part, g_part);

    // conv1 + square
    conv1_v2<<<dim3(28, 3, 64), dim3(28, 4)>>>(x, w1, b1, a1);
    // pool1: 55 -> 27
    {
        int total = 64*96*27*27;
        avgpool_kernel<<<(total + 255)/256, 256>>>(a1, p1, 55, 27, total);
    }
    // conv2 + square
    conv2_v2<<<dim3(3, 8, 64), dim3(7, 9, 4)>>>(p1, w2, b2, a2);
    // pool2: 27 -> 13
    {
        int total = 64*256*13*13;
        avgpool_kernel<<<(total + 255)/256, 256>>>(a2, p2, 27, 13, total);
    }
    // conv3/4/5 + square
    conv3_v2<256><<<dim3(12, 64), dim3(13, 16)>>>(p2, w3, b3, a3, 384);
    conv3_v2<384><<<dim3(12, 64), dim3(13, 16)>>>(a3, w4, b4, a4, 384);
    conv3_v2<384><<<dim3(8, 64),  dim3(13, 16)>>>(a4, w5, b5, a5, 256);
    // pool3: 13 -> 6
    {
        int total = 64*256*6*6;
        avgpool_kernel<<<(total + 255)/256, 256>>>(a5, p3, 13, 6, total);
    }
    // fc1: [64,9216] x [9216,4096]
    fc_partial<16><<<dim3(32, 4, 4), 128>>>(p3, fw1, part, 9216, 4096, 4);
    fc_reduce<<<(64*4096 + 255)/256, 256>>>(part, fb1, f1, 4096, 4, 64*4096);
    // fc2: [64,4096] x [4096,4096]
    fc_partial<16><<<dim3(32, 4, 4), 128>>>(f1, fw2, part, 4096, 4096, 4);
    fc_reduce<<<(64*4096 + 255)/256, 256>>>(part, fb2, f2, 4096, 4, 64*4096);
    // fc3: [64,4096] x [4096,1000]
    fc_partial<16><<<dim3(8, 4, 4), 128>>>(f2, fw3, part, 4096, 1000, 4);
    fc_reduce<<<(64*1000 + 255)/256, 256>>>(part, fb3, out, 1000, 4, 64*1000);
}

// round 5
// speedup vs baseline: 4.6888x; 1.4923x over previous
#include <cuda_runtime.h>
#include <cuda_bf16.h>
#include <cstddef>
#include <cstdint>

// ---------------- scratch ----------------
__device__ __align__(16) float g_a1[64*96*55*55];
__device__ __align__(16) float g_p1[64*96*27*27];
__device__ __align__(16) float g_a2t[256*27*27*64];   // conv2 out CHWN fp32
__device__ __align__(16) float g_a5t[256*13*13*64];   // conv5 out CHWN fp32
__device__ __align__(16) float g_p3[64*256*6*6];
__device__ __align__(16) float g_f1[64*4096];
__device__ __align__(16) float g_f2[64*4096];
__device__ __align__(16) float g_part[4*64*4096];

// CHWN split-bf16 activations with halo
__device__ __align__(16) __nv_bfloat16 g_xt2h[96*31*32*64];
__device__ __align__(16) __nv_bfloat16 g_xt2l[96*31*32*64];
__device__ __align__(16) __nv_bfloat16 g_xt3h[256*15*16*64];
__device__ __align__(16) __nv_bfloat16 g_xt3l[256*15*16*64];
__device__ __align__(16) __nv_bfloat16 g_xt4h[384*15*16*64];
__device__ __align__(16) __nv_bfloat16 g_xt4l[384*15*16*64];
__device__ __align__(16) __nv_bfloat16 g_xt5h[384*15*16*64];
__device__ __align__(16) __nv_bfloat16 g_xt5l[384*15*16*64];
// pre-packed swizzled weight A-tiles: [cotile][kblk][128co x 32k]
__device__ __align__(16) __nv_bfloat16 g_w2h[2*75*4096];
__device__ __align__(16) __nv_bfloat16 g_w2l[2*75*4096];
__device__ __align__(16) __nv_bfloat16 g_w3h[3*72*4096];
__device__ __align__(16) __nv_bfloat16 g_w3l[3*72*4096];
__device__ __align__(16) __nv_bfloat16 g_w4h[3*108*4096];
__device__ __align__(16) __nv_bfloat16 g_w4l[3*108*4096];
__device__ __align__(16) __nv_bfloat16 g_w5h[2*108*4096];
__device__ __align__(16) __nv_bfloat16 g_w5l[2*108*4096];

// ---------------- warp mma helpers ----------------
__device__ __forceinline__ uint32_t smem_u32(const void* p) {
    uint32_t a; asm("{ .reg .u64 t; cvta.to.shared.u64 t, %1; cvt.u32.u64 %0, t; }" : "=r"(a) : "l"(p)); return a;
}
__device__ __forceinline__ void mma_bf16(float* c, const unsigned* a, const unsigned* b) {
    asm volatile("mma.sync.aligned.m16n8k16.row.col.f32.bf16.bf16.f32 "
        "{%0,%1,%2,%3}, {%4,%5,%6,%7}, {%8,%9}, {%0,%1,%2,%3};"
        : "+f"(c[0]), "+f"(c[1]), "+f"(c[2]), "+f"(c[3])
        : "r"(a[0]), "r"(a[1]), "r"(a[2]), "r"(a[3]), "r"(b[0]), "r"(b[1]));
}
__device__ __forceinline__ void ldsm_x4(unsigned* r, uint32_t addr) {
    asm volatile("ldmatrix.sync.aligned.m8n8.x4.shared.b16 {%0,%1,%2,%3}, [%4];"
        : "=r"(r[0]), "=r"(r[1]), "=r"(r[2]), "=r"(r[3]) : "r"(addr));
}
__device__ __forceinline__ void ldsm_x2t(unsigned* r, uint32_t addr) {
    asm volatile("ldmatrix.sync.aligned.m8n8.x2.trans.shared.b16 {%0,%1}, [%2];"
        : "=r"(r[0]), "=r"(r[1]) : "r"(addr));
}
__device__ __forceinline__ uint32_t pack_bf(__nv_bfloat16 lo, __nv_bfloat16 hi) {
    return ((uint32_t)__bfloat16_as_ushort(hi) << 16) | __bfloat16_as_ushort(lo);
}

// ================= mma conv: stride-1, KSxKS, pad, HxH, CHWN split-bf16 =================
// CTA = one output pixel x 128 co. C[128co x 64n] fp32 via 3-term bf16 split.
template<int CIN, int KS, int H, int PAD, int OUT_XT>
__global__ __launch_bounds__(256) void mconv(
    const __nv_bfloat16* __restrict__ xh, const __nv_bfloat16* __restrict__ xl,
    const __nv_bfloat16* __restrict__ wh, const __nv_bfloat16* __restrict__ wl,
    const float* __restrict__ bias,
    __nv_bfloat16* __restrict__ oxh, __nv_bfloat16* __restrict__ oxl,
    float* __restrict__ ofp)
{
    constexpr int HH = H + 2*PAD;
    constexpr int WP = ((HH + 15)/16)*16;
    constexpr int CB = CIN/32;
    constexpr int NKB = KS*KS*CB;

    __shared__ __align__(16) __nv_bfloat16 sA[2][4096];  // [h/l][128co*32k] swizzled
    __shared__ __align__(16) __nv_bfloat16 sB[2][2048];  // [h/l][32k*64n] swizzled

    const int tid = threadIdx.x;
    const int warp = tid >> 5, lane = tid & 31;
    const int wm = warp & 3, wn = warp >> 2;
    const int p = blockIdx.x;
    const int oh = p / H, ow = p % H;
    const int cotile = blockIdx.y;

    const uint32_t sAh32 = smem_u32(sA[0]);
    const uint32_t sAl32 = smem_u32(sA[1]);
    const uint32_t sBh32 = smem_u32(sB[0]);
    const uint32_t sBl32 = smem_u32(sB[1]);

    float C[2][4][4];
    #pragma unroll
    for (int a = 0; a < 2; ++a)
        #pragma unroll
        for (int b = 0; b < 4; ++b)
            #pragma unroll
            for (int c = 0; c < 4; ++c) C[a][b][c] = 0.f;

    const int br = tid >> 3, bu = tid & 7;
    const uint32_t bdst = br*128 + ((bu*16) ^ ((br & 7) << 4));

    for (int kb = 0; kb < NKB; ++kb) {
        __syncthreads();
        // stage A (8KB hi + 8KB lo, pre-swizzled flat copy)
        const uint4* srcAh = (const uint4*)(wh + ((size_t)(cotile*NKB + kb) << 12));
        const uint4* srcAl = (const uint4*)(wl + ((size_t)(cotile*NKB + kb) << 12));
        ((uint4*)sA[0])[tid]       = srcAh[tid];
        ((uint4*)sA[0])[tid + 256] = srcAh[tid + 256];
        ((uint4*)sA[1])[tid]       = srcAl[tid];
        ((uint4*)sA[1])[tid + 256] = srcAl[tid + 256];
        // stage B: 32 rows (k = ci), 128B each, swizzled
        const int tap = kb / CB;
        const int ci  = (kb % CB)*32 + br;
        const int kh = tap / KS, kw = tap % KS;
        const size_t bsrc = (((size_t)ci*HH + (oh + kh))*WP + (ow + kw))*64 + bu*8;
        *(uint4*)((char*)sB[0] + bdst) = *(const uint4*)(xh + bsrc);
        *(uint4*)((char*)sB[1] + bdst) = *(const uint4*)(xl + bsrc);
        __syncthreads();

        #pragma unroll
        for (int kc = 0; kc < 2; ++kc) {
            unsigned ah[2][4], al[2][4], bh[4][2], bl[4][2];
            #pragma unroll
            for (int mt = 0; mt < 2; ++mt) {
                const int q = lane >> 3, r = lane & 7;
                const int row = wm*32 + mt*16 + (q & 1)*8 + r;
                const uint32_t off = row*64 + ((kc*32 + (q >> 1)*16) ^ ((row & 3) << 4));
                ldsm_x4(ah[mt], sAh32 + off);
                ldsm_x4(al[mt], sAl32 + off);
            }
            #pragma unroll
            for (int nt = 0; nt < 4; ++nt) {
                const int l = lane & 15;
                const int k = kc*16 + l;
                const int n0 = wn*32 + nt*8;
                const uint32_t off = k*128 + ((n0*2) ^ ((k & 7) << 4));
                ldsm_x2t(bh[nt], sBh32 + off);
                ldsm_x2t(bl[nt], sBl32 + off);
            }
            #pragma unroll
            for (int mt = 0; mt < 2; ++mt)
                #pragma unroll
                for (int nt = 0; nt < 4; ++nt) {
                    mma_bf16(C[mt][nt], ah[mt], bh[nt]);
                    mma_bf16(C[mt][nt], ah[mt], bl[nt]);
                    mma_bf16(C[mt][nt], al[mt], bh[nt]);
                }
        }
    }

    // epilogue: v = acc + b + 1; out = v*v
    const int g = lane >> 2, tg = lane & 3;
    #pragma unroll
    for (int mt = 0; mt < 2; ++mt) {
        #pragma unroll
        for (int hlf = 0; hlf < 2; ++hlf) {
            const int co = cotile*128 + wm*32 + mt*16 + hlf*8 + g;
            const float vb = bias[co] + 1.0f;
            #pragma unroll
            for (int nt = 0; nt < 4; ++nt) {
                const int n = wn*32 + nt*8 + tg*2;
                float v0 = C[mt][nt][hlf*2 + 0] + vb;
                float v1 = C[mt][nt][hlf*2 + 1] + vb;
                const float s0 = v0*v0, s1 = v1*v1;
                if (OUT_XT) {
                    const __nv_bfloat16 h0 = __float2bfloat16(s0);
                    const __nv_bfloat16 h1 = __float2bfloat16(s1);
                    const __nv_bfloat16 l0 = __float2bfloat16(s0 - __bfloat162float(h0));
                    const __nv_bfloat16 l1 = __float2bfloat16(s1 - __bfloat162float(h1));
                    const size_t o = (((size_t)co*HH + (oh + PAD))*WP + (ow + PAD))*64 + n;
                    *(uint32_t*)(oxh + o) = pack_bf(h0, h1);
                    *(uint32_t*)(oxl + o) = pack_bf(l0, l1);
                } else {
                    const size_t o = (((size_t)co*H + oh)*H + ow)*64 + n;
                    *(float2*)(ofp + o) = make_float2(s0, s1);
                }
            }
        }
    }
}

// ---------------- weight prep -> swizzled [128x32] A tiles ----------------
__global__ void prep_w(const float* __restrict__ w, __nv_bfloat16* __restrict__ dh,
                       __nv_bfloat16* __restrict__ dl, int CIN, int KS2, int CB, int NKB, int total)
{
    int idx = blockIdx.x * blockDim.x + threadIdx.x;
    if (idx >= total) return;
    const int e = idx & 4095;
    const int kb = (idx >> 12) % NKB;
    const int cotile = idx / (NKB * 4096);
    const int co = e >> 5, kk = e & 31;
    const int tap = kb / CB;
    const int ci = (kb % CB)*32 + kk;
    const float val = w[((size_t)(cotile*128 + co)*CIN + ci)*KS2 + tap];
    const __nv_bfloat16 hv = __float2bfloat16(val);
    const __nv_bfloat16 lv = __float2bfloat16(val - __bfloat162float(hv));
    const size_t o = ((size_t)(cotile*NKB + kb) << 12) + co*32 + (kk ^ ((co & 3) << 3));
    dh[o] = hv; dl[o] = lv;
}

// ---------------- NCHW fp32 [64][96][27][27] -> CHWN split-bf16 halo2 [96][31][32][64] ----------------
__global__ __launch_bounds__(128) void to_chwn27(
    const float* __restrict__ x, __nv_bfloat16* __restrict__ dh, __nv_bfloat16* __restrict__ dl)
{
    __shared__ float s[27][64];
    const int ci = blockIdx.y;     // 96
    const int ih = blockIdx.x;     // 27
    const int tid = threadIdx.x;
    for (int i = tid; i < 27*64; i += 128) {
        const int n = i / 27, iw = i % 27;
        s[iw][n] = x[(((size_t)n*96 + ci)*27 + ih)*27 + iw];
    }
    __syncthreads();
    for (int i = tid; i < 27*64; i += 128) {
        const int iw = i >> 6, n = i & 63;
        const float v = s[iw][n];
        const __nv_bfloat16 hv = __float2bfloat16(v);
        const __nv_bfloat16 lv = __float2bfloat16(v - __bfloat162float(hv));
        const size_t o = (((size_t)ci*31 + ih + 2)*32 + iw + 2)*64 + n;
        dh[o] = hv; dl[o] = lv;
    }
}

// ---------------- pool2: CHWN fp32 27x27 -> CHWN split-bf16 halo1 13x13 ----------------
__global__ void pool2_chwn(const float* __restrict__ x, __nv_bfloat16* __restrict__ dh,
                           __nv_bfloat16* __restrict__ dl, int total)
{
    int idx = blockIdx.x * blockDim.x + threadIdx.x;
    if (idx >= total) return;
    const int n = idx & 63;
    int r = idx >> 6;
    const int ow = r % 13; r /= 13;
    const int oh = r % 13; r /= 13;
    const int co = r;      // 0..255
    float s = 0.f;
    #pragma unroll
    for (int i = 0; i < 3; ++i)
        #pragma unroll
        for (int j = 0; j < 3; ++j)
            s += x[(((size_t)co*27 + (oh*2 + i))*27 + (ow*2 + j))*64 + n];
    const float v = s * (1.0f/9.0f);
    const __nv_bfloat16 hv = __float2bfloat16(v);
    const __nv_bfloat16 lv = __float2bfloat16(v - __bfloat162float(hv));
    const size_t o = (((size_t)co*15 + oh + 1)*16 + ow + 1)*64 + n;
    dh[o] = hv; dl[o] = lv;
}

// ---------------- pool3: CHWN fp32 13x13 -> NCHW flatten 6x6 ----------------
__global__ void pool3_chwn(const float* __restrict__ x, float* __restrict__ y, int total)
{
    int idx = blockIdx.x * blockDim.x + threadIdx.x;
    if (idx >= total) return;
    const int n = idx & 63;
    int r = idx >> 6;
    const int ow = r % 6; r /= 6;
    const int oh = r % 6; r /= 6;
    const int co = r;      // 0..255
    float s = 0.f;
    #pragma unroll
    for (int i = 0; i < 3; ++i)
        #pragma unroll
        for (int j = 0; j < 3; ++j)
            s += x[(((size_t)co*13 + (oh*2 + i))*13 + (ow*2 + j))*64 + n];
    y[(size_t)n*9216 + co*36 + oh*6 + ow] = s * (1.0f/9.0f);
}

// ================= conv1 (fp32) =================
__global__ __launch_bounds__(112) void conv1_v2(
    const float* __restrict__ x, const float* __restrict__ w,
    const float* __restrict__ b, float* __restrict__ y)
{
    __shared__ __align__(16) float xs[4][15][58];
    __shared__ __align__(16) float ws[32][121];
    const int tx = threadIdx.x, ty = threadIdx.y;
    const int tid = ty*28 + tx;
    const int blk = blockIdx.x;
    const int co0 = blockIdx.y * 32;
    const int n   = blockIdx.z;
    const int ih0 = blk * 8;

    for (int i = tid; i < 4*15*58; i += 112) ((float*)xs)[i] = 0.f;

    float acc[2][2][8];
    #pragma unroll
    for (int o = 0; o < 2; ++o)
        #pragma unroll
        for (int j = 0; j < 2; ++j)
            #pragma unroll
            for (int cc = 0; cc < 8; ++cc) acc[o][j][cc] = 0.f;

    const float* xn = x + (size_t)n * (3*227*227);
    for (int c = 0; c < 3; ++c) {
        __syncthreads();
        for (int i = tid; i < 32*121; i += 112) {
            int ci = i / 121, k = i % 121;
            ws[ci][k] = w[(size_t)(co0+ci)*363 + c*121 + k];
        }
        for (int i = tid; i < 15*227; i += 112) {
            int r = i / 227, iw = i % 227;
            int ih = ih0 + r;
            xs[iw & 3][r][iw >> 2] = (ih < 227) ? xn[((size_t)c*227 + ih)*227 + iw] : 0.f;
        }
        __syncthreads();
        #pragma unroll
        for (int kh = 0; kh < 11; ++kh) {
            #pragma unroll
            for (int kw = 0; kw < 11; ++kw) {
                const int kr = kw & 3, kq = kw >> 2;
                const float x00 = xs[kr][kh][tx + kq];
                const float x01 = xs[kr][kh][tx + 28 + kq];
                const float x10 = xs[kr][kh + 4][tx + kq];
                const float x11 = xs[kr][kh + 4][tx + 28 + kq];
                #pragma unroll
                for (int cc = 0; cc < 8; ++cc) {
                    const float wv = ws[ty*8 + cc][kh*11 + kw];
                    acc[0][0][cc] += wv * x00;
                    acc[0][1][cc] += wv * x01;
                    acc[1][0][cc] += wv * x10;
                    acc[1][1][cc] += wv * x11;
                }
            }
        }
    }
    #pragma unroll
    for (int cc = 0; cc < 8; ++cc) {
        const int co = co0 + ty*8 + cc;
        const float vb = b[co] + 1.0f;
        #pragma unroll
        for (int o = 0; o < 2; ++o) {
            const int oh = blk*2 + o;
            if (oh >= 55) continue;
            #pragma unroll
            for (int j = 0; j < 2; ++j) {
                const int ow = tx + 28*j;
                if (ow >= 55) continue;
                float v = acc[o][j][cc] + vb;
                y[(((size_t)n*96 + co)*55 + oh)*55 + ow] = v*v;
            }
        }
    }
}

// ---------------- 3x3 s2 avg pool (NCHW) ----------------
__global__ void avgpool_kernel(const float* __restrict__ x, float* __restrict__ y,
                               int H, int OH, int total)
{
    int idx = blockIdx.x*blockDim.x + threadIdx.x;
    if (idx >= total) return;
    int ow = idx % OH; int t = idx / OH;
    int oh = t % OH;   t /= OH;
    const float* xp = x + ((size_t)t*H + oh*2)*H + ow*2;
    float s = 0.f;
    #pragma unroll
    for (int i = 0; i < 3; ++i)
        #pragma unroll
        for (int j = 0; j < 3; ++j) s += xp[i*H + j];
    y[idx] = s * (1.0f/9.0f);
}

// ---------------- FC ----------------
template<int MROWS>
__global__ __launch_bounds__(128) void fc_partial(
    const float* __restrict__ x, const float* __restrict__ w,
    float* __restrict__ part, int K, int N, int S)
{
    const int n  = blockIdx.x*128 + threadIdx.x;
    const int m0 = blockIdx.y * MROWS;
    const int s  = blockIdx.z;
    const int kc = K / S;
    const int k0 = s*kc, k1 = k0 + kc;

    __shared__ float xs[MROWS][32];
    float acc[MROWS];
    #pragma unroll
    for (int i = 0; i < MROWS; ++i) acc[i] = 0.f;

    for (int kt = k0; kt < k1; kt += 32) {
        __syncthreads();
        for (int i = threadIdx.x; i < MROWS*32; i += 128) {
            int mm = i >> 5, kk = i & 31;
            xs[mm][kk] = x[(size_t)(m0+mm)*K + kt + kk];
        }
        __syncthreads();
        if (n < N) {
            #pragma unroll
            for (int kk = 0; kk < 32; kk += 4) {
                const float w0 = w[(size_t)(kt+kk  )*N + n];
                const float w1 = w[(size_t)(kt+kk+1)*N + n];
                const float w2 = w[(size_t)(kt+kk+2)*N + n];
                const float w3 = w[(size_t)(kt+kk+3)*N + n];
                #pragma unroll
                for (int mm = 0; mm < MROWS; ++mm) {
                    const float4 xv = *reinterpret_cast<const float4*>(&xs[mm][kk]);
                    acc[mm] += xv.x*w0 + xv.y*w1 + xv.z*w2 + xv.w*w3;
                }
            }
        }
    }
    if (n < N) {
        #pragma unroll
        for (int mm = 0; mm < MROWS; ++mm)
            part[((size_t)s*64 + m0 + mm)*N + n] = acc[mm];
    }
}

__global__ void fc_reduce(const float* __restrict__ part, const float* __restrict__ bias,
                          float* __restrict__ out, int N, int S, int total)
{
    int idx = blockIdx.x*blockDim.x + threadIdx.x;
    if (idx >= total) return;
    int n = idx % N;
    float s = bias[n];
    for (int i = 0; i < S; ++i) s += part[(size_t)i*64*N + idx];
    out[idx] = s;
}

// ---------------- host launcher ----------------
extern "C" void kernel_launch(void* const* d_in, const int* in_sizes, int n_in,
                              void* d_out, int out_size)
{
    const float* x   = (const float*)d_in[0];
    const float* w1  = (const float*)d_in[1];
    const float* b1  = (const float*)d_in[2];
    const float* w2  = (const float*)d_in[3];
    const float* b2  = (const float*)d_in[4];
    const float* w3  = (const float*)d_in[5];
    const float* b3  = (const float*)d_in[6];
    const float* w4  = (const float*)d_in[7];
    const float* b4  = (const float*)d_in[8];
    const float* w5  = (const float*)d_in[9];
    const float* b5  = (const float*)d_in[10];
    const float* fw1 = (const float*)d_in[11];
    const float* fb1 = (const float*)d_in[12];
    const float* fw2 = (const float*)d_in[13];
    const float* fb2 = (const float*)d_in[14];
    const float* fw3 = (const float*)d_in[15];
    const float* fb3 = (const float*)d_in[16];
    float* out = (float*)d_out;

    float *a1,*p1,*a2t,*a5t,*p3,*f1,*f2,*part;
    __nv_bfloat16 *xt2h,*xt2l,*xt3h,*xt3l,*xt4h,*xt4l,*xt5h,*xt5l;
    __nv_bfloat16 *w2h,*w2l,*w3h,*w3l,*w4h,*w4l,*w5h,*w5l;
    cudaGetSymbolAddress((void**)&a1, g_a1);
    cudaGetSymbolAddress((void**)&p1, g_p1);
    cudaGetSymbolAddress((void**)&a2t, g_a2t);
    cudaGetSymbolAddress((void**)&a5t, g_a5t);
    cudaGetSymbolAddress((void**)&p3, g_p3);
    cudaGetSymbolAddress((void**)&f1, g_f1);
    cudaGetSymbolAddress((void**)&f2, g_f2);
    cudaGetSymbolAddress((void**)&part, g_part);
    cudaGetSymbolAddress((void**)&xt2h, g_xt2h);
    cudaGetSymbolAddress((void**)&xt2l, g_xt2l);
    cudaGetSymbolAddress((void**)&xt3h, g_xt3h);
    cudaGetSymbolAddress((void**)&xt3l, g_xt3l);
    cudaGetSymbolAddress((void**)&xt4h, g_xt4h);
    cudaGetSymbolAddress((void**)&xt4l, g_xt4l);
    cudaGetSymbolAddress((void**)&xt5h, g_xt5h);
    cudaGetSymbolAddress((void**)&xt5l, g_xt5l);
    cudaGetSymbolAddress((void**)&w2h, g_w2h);
    cudaGetSymbolAddress((void**)&w2l, g_w2l);
    cudaGetSymbolAddress((void**)&w3h, g_w3h);
    cudaGetSymbolAddress((void**)&w3l, g_w3l);
    cudaGetSymbolAddress((void**)&w4h, g_w4h);
    cudaGetSymbolAddress((void**)&w4l, g_w4l);
    cudaGetSymbolAddress((void**)&w5h, g_w5h);
    cudaGetSymbolAddress((void**)&w5l, g_w5l);

    // zero halo'd activation tensors
    cudaMemsetAsync(xt2h, 0, sizeof(g_xt2h));
    cudaMemsetAsync(xt2l, 0, sizeof(g_xt2l));
    cudaMemsetAsync(xt3h, 0, sizeof(g_xt3h));
    cudaMemsetAsync(xt3l, 0, sizeof(g_xt3l));
    cudaMemsetAsync(xt4h, 0, sizeof(g_xt4h));
    cudaMemsetAsync(xt4l, 0, sizeof(g_xt4l));
    cudaMemsetAsync(xt5h, 0, sizeof(g_xt5h));
    cudaMemsetAsync(xt5l, 0, sizeof(g_xt5l));

    // weight prep
    { int tot = 2*75*4096;  prep_w<<<(tot+255)/256, 256>>>(w2, w2h, w2l,  96, 25,  3,  75, tot); }
    { int tot = 3*72*4096;  prep_w<<<(tot+255)/256, 256>>>(w3, w3h, w3l, 256,  9,  8,  72, tot); }
    { int tot = 3*108*4096; prep_w<<<(tot+255)/256, 256>>>(w4, w4h, w4l, 384,  9, 12, 108, tot); }
    { int tot = 2*108*4096; prep_w<<<(tot+255)/256, 256>>>(w5, w5h, w5l, 384,  9, 12, 108, tot); }

    // conv1 + pool1 (fp32 NCHW)
    conv1_v2<<<dim3(28, 3, 64), dim3(28, 4)>>>(x, w1, b1, a1);
    { int t = 64*96*27*27; avgpool_kernel<<<(t+255)/256, 256>>>(a1, p1, 55, 27, t); }
    // convert to CHWN split-bf16 halo2
    to_chwn27<<<dim3(27, 96), 128>>>(p1, xt2h, xt2l);
    // conv2 (mma) -> fp32 CHWN
    mconv<96,5,27,2,0><<<dim3(729, 2), 256>>>(xt2h, xt2l, w2h, w2l, b2, nullptr, nullptr, a2t);
    // pool2 -> CHWN split-bf16 halo1
    { int t = 256*13*13*64; pool2_chwn<<<(t+255)/256, 256>>>(a2t, xt3h, xt3l, t); }
    // conv3/4/5 (mma)
    mconv<256,3,13,1,1><<<dim3(169, 3), 256>>>(xt3h, xt3l, w3h, w3l, b3, xt4h, xt4l, nullptr);
    mconv<384,3,13,1,1><<<dim3(169, 3), 256>>>(xt4h, xt4l, w4h, w4l, b4, xt5h, xt5l, nullptr);
    mconv<384,3,13,1,0><<<dim3(169, 2), 256>>>(xt5h, xt5l, w5h, w5l, b5, nullptr, nullptr, a5t);
    // pool3 -> NCHW flatten
    { int t = 64*256*36; pool3_chwn<<<(t+255)/256, 256>>>(a5t, p3, t); }

    // FC
    fc_partial<16><<<dim3(32, 4, 4), 128>>>(p3, fw1, part, 9216, 4096, 4);
    fc_reduce<<<(64*4096 + 255)/256, 256>>>(part, fb1, f1, 4096, 4, 64*4096);
    fc_partial<16><<<dim3(32, 4, 4), 128>>>(f1, fw2, part, 4096, 4096, 4);
    fc_reduce<<<(64*4096 + 255)/256, 256>>>(part, fb2, f2, 4096, 4, 64*4096);
    fc_partial<16><<<dim3(8, 4, 4), 128>>>(f2, fw3, part, 4096, 1000, 4);
    fc_reduce<<<(64*1000 + 255)/256, 256>>>(part, fb3, out, 1000, 4, 64*1000);
}

// round 7
// speedup vs baseline: 6.6932x; 1.4275x over previous
#include <cuda_runtime.h>
#include <cuda_bf16.h>
#include <cstddef>
#include <cstdint>

// ---------------- scratch ----------------
__device__ __align__(16) float g_a1[64*96*55*55];
__device__ __align__(16) float g_p1[64*96*27*27];
__device__ __align__(16) float g_a2t[256*27*27*64];   // conv2 out CHWN fp32
__device__ __align__(16) float g_a5t[256*13*13*64];   // conv5 out CHWN fp32
__device__ __align__(16) float g_p3[64*256*6*6];
__device__ __align__(16) float g_f1[64*4096];
__device__ __align__(16) float g_f2[64*4096];
__device__ __align__(16) float g_part[8*64*4096];

// CHWN split-bf16 activations with halo
__device__ __align__(16) __nv_bfloat16 g_xt2h[96*31*32*64];
__device__ __align__(16) __nv_bfloat16 g_xt2l[96*31*32*64];
__device__ __align__(16) __nv_bfloat16 g_xt3h[256*15*16*64];
__device__ __align__(16) __nv_bfloat16 g_xt3l[256*15*16*64];
__device__ __align__(16) __nv_bfloat16 g_xt4h[384*15*16*64];
__device__ __align__(16) __nv_bfloat16 g_xt4l[384*15*16*64];
__device__ __align__(16) __nv_bfloat16 g_xt5h[384*15*16*64];
__device__ __align__(16) __nv_bfloat16 g_xt5l[384*15*16*64];
// pre-packed swizzled weight A-tiles: [cotile][kblk][128co x 32k]
__device__ __align__(16) __nv_bfloat16 g_w2h[2*75*4096];
__device__ __align__(16) __nv_bfloat16 g_w2l[2*75*4096];
__device__ __align__(16) __nv_bfloat16 g_w3h[3*72*4096];
__device__ __align__(16) __nv_bfloat16 g_w3l[3*72*4096];
__device__ __align__(16) __nv_bfloat16 g_w4h[3*108*4096];
__device__ __align__(16) __nv_bfloat16 g_w4l[3*108*4096];
__device__ __align__(16) __nv_bfloat16 g_w5h[2*108*4096];
__device__ __align__(16) __nv_bfloat16 g_w5l[2*108*4096];

// ---------------- helpers ----------------
__device__ __forceinline__ uint32_t smem_u32(const void* p) {
    uint32_t a; asm("{ .reg .u64 t; cvta.to.shared.u64 t, %1; cvt.u32.u64 %0, t; }" : "=r"(a) : "l"(p)); return a;
}
__device__ __forceinline__ void mma_bf16(float* c, const unsigned* a, const unsigned* b) {
    asm volatile("mma.sync.aligned.m16n8k16.row.col.f32.bf16.bf16.f32 "
        "{%0,%1,%2,%3}, {%4,%5,%6,%7}, {%8,%9}, {%0,%1,%2,%3};"
        : "+f"(c[0]), "+f"(c[1]), "+f"(c[2]), "+f"(c[3])
        : "r"(a[0]), "r"(a[1]), "r"(a[2]), "r"(a[3]), "r"(b[0]), "r"(b[1]));
}
__device__ __forceinline__ void ldsm_x4(unsigned* r, uint32_t addr) {
    asm volatile("ldmatrix.sync.aligned.m8n8.x4.shared.b16 {%0,%1,%2,%3}, [%4];"
        : "=r"(r[0]), "=r"(r[1]), "=r"(r[2]), "=r"(r[3]) : "r"(addr));
}
__device__ __forceinline__ void ldsm_x2t(unsigned* r, uint32_t addr) {
    asm volatile("ldmatrix.sync.aligned.m8n8.x2.trans.shared.b16 {%0,%1}, [%2];"
        : "=r"(r[0]), "=r"(r[1]) : "r"(addr));
}
__device__ __forceinline__ uint32_t pack_bf(__nv_bfloat16 lo, __nv_bfloat16 hi) {
    return ((uint32_t)__bfloat16_as_ushort(hi) << 16) | __bfloat16_as_ushort(lo);
}
__device__ __forceinline__ void cp_async16(uint32_t dst, const void* src) {
    asm volatile("cp.async.cg.shared.global [%0], [%1], 16;" :: "r"(dst), "l"(src));
}
#define CP_COMMIT() asm volatile("cp.async.commit_group;" ::: "memory")
#define CP_WAIT0()  asm volatile("cp.async.wait_group 0;" ::: "memory")
__device__ __forceinline__ void fma2(unsigned long long &acc, unsigned long long a, unsigned long long b) {
    asm("fma.rn.f32x2 %0, %1, %2, %0;" : "+l"(acc) : "l"(a), "l"(b));
}
__device__ __forceinline__ unsigned long long pk2(float lo, float hi) {
    unsigned long long r; asm("mov.b64 %0, {%1, %2};" : "=l"(r) : "f"(lo), "f"(hi)); return r;
}
__device__ __forceinline__ void upk2(float &lo, float &hi, unsigned long long v) {
    asm("mov.b64 {%0, %1}, %2;" : "=f"(lo), "=f"(hi) : "l"(v));
}

// ================= mma conv v2: 2 pixels/CTA, cp.async double-buffered =================
// C[128co x (2pix*64n)] fp32 via 3-term bf16 split. Buffer layout (bytes, per 32KB buffer):
//   [0,8K) A_h | [8K,16K) A_l | [16K+p*4K) B_h pix p | [24K+p*4K) B_l pix p
template<int CIN, int KS, int H, int PAD, int OUT_XT>
__global__ __launch_bounds__(256) void mconv2(
    const __nv_bfloat16* __restrict__ xh, const __nv_bfloat16* __restrict__ xl,
    const __nv_bfloat16* __restrict__ wh, const __nv_bfloat16* __restrict__ wl,
    const float* __restrict__ bias,
    __nv_bfloat16* __restrict__ oxh, __nv_bfloat16* __restrict__ oxl,
    float* __restrict__ ofp)
{
    extern __shared__ __align__(16) char smem[];
    constexpr int HH = H + 2*PAD;
    constexpr int WP = ((HH + 15)/16)*16;
    constexpr int CB = CIN/32;
    constexpr int NKB = KS*KS*CB;
    constexpr int OWP = (H + 1)/2;

    const int tid = threadIdx.x;
    const int warp = tid >> 5, lane = tid & 31;
    const int wm = warp & 3, wn = warp >> 2;   // wn = pixel
    const int bx = blockIdx.x;
    const int oh = bx / OWP, ow0 = (bx % OWP)*2;
    const int npx = (ow0 + 1 < H) ? 2 : 1;
    const int cotile = blockIdx.y;
    const uint32_t sb = smem_u32(smem);

    // staging thread mapping for B
    const int sr = tid >> 3, su = tid & 7;
    const uint32_t brow = sr*128 + ((su*16) ^ ((sr & 7) << 4));

    auto stage = [&](int kb, int bb) {
        const uint32_t base = sb + bb*32768;
        const size_t wbase16 = ((size_t)(cotile*NKB + kb)) << 13;  // byte offset (4096 bf16)
        #pragma unroll
        for (int j = 0; j < 2; ++j) {
            const int c = tid + j*256;
            cp_async16(base + c*16,        (const char*)wh + wbase16 + c*16);
            cp_async16(base + 8192 + c*16, (const char*)wl + wbase16 + c*16);
        }
        const int tap = kb / CB, ci0 = (kb % CB)*32;
        const int kh = tap / KS, kw = tap % KS;
        #pragma unroll
        for (int p = 0; p < 2; ++p) {
            const int ow = (p < npx) ? (ow0 + p) : ow0;
            const size_t src = (((size_t)(ci0 + sr)*HH + oh + kh)*WP + ow + kw)*64 + su*8;
            cp_async16(base + 16384 + p*4096 + brow, xh + src);
            cp_async16(base + 24576 + p*4096 + brow, xl + src);
        }
    };

    float C[2][8][4];
    #pragma unroll
    for (int a = 0; a < 2; ++a)
        #pragma unroll
        for (int b = 0; b < 8; ++b)
            #pragma unroll
            for (int c = 0; c < 4; ++c) C[a][b][c] = 0.f;

    stage(0, 0); CP_COMMIT();
    int cur = 0;

    for (int kb = 0; kb < NKB; ++kb) {
        CP_WAIT0();
        __syncthreads();
        if (kb + 1 < NKB) { stage(kb + 1, cur ^ 1); CP_COMMIT(); }

        const uint32_t bA = sb + cur*32768;
        const uint32_t bB = bA + 16384 + wn*4096;
        const int q = lane >> 3, rr = lane & 7;
        #pragma unroll
        for (int kc = 0; kc < 2; ++kc) {
            unsigned ah[2][4], al[2][4];
            #pragma unroll
            for (int mt = 0; mt < 2; ++mt) {
                const int row = wm*32 + mt*16 + (q & 1)*8 + rr;
                const uint32_t off = row*64 + ((kc*32 + (q >> 1)*16) ^ ((row & 3) << 4));
                ldsm_x4(ah[mt], bA + off);
                ldsm_x4(al[mt], bA + 8192 + off);
            }
            const int k = kc*16 + (lane & 15);
            #pragma unroll
            for (int nt = 0; nt < 8; ++nt) {
                unsigned bh[2], bl[2];
                const uint32_t off = k*128 + ((nt*16) ^ ((k & 7) << 4));
                ldsm_x2t(bh, bB + off);
                ldsm_x2t(bl, bB + 8192 + off);
                #pragma unroll
                for (int mt = 0; mt < 2; ++mt) {
                    mma_bf16(C[mt][nt], ah[mt], bh);
                    mma_bf16(C[mt][nt], ah[mt], bl);
                    mma_bf16(C[mt][nt], al[mt], bh);
                }
            }
        }
        cur ^= 1;
    }

    // epilogue: v = acc + b + 1; out = v*v
    const int p = wn;
    if (p >= npx) return;
    const int ow = ow0 + p;
    const int g = lane >> 2, tg = lane & 3;
    #pragma unroll
    for (int mt = 0; mt < 2; ++mt) {
        #pragma unroll
        for (int hlf = 0; hlf < 2; ++hlf) {
            const int co = cotile*128 + wm*32 + mt*16 + hlf*8 + g;
            const float vb = bias[co] + 1.0f;
            #pragma unroll
            for (int nt = 0; nt < 8; ++nt) {
                const int n = nt*8 + tg*2;
                float v0 = C[mt][nt][hlf*2 + 0] + vb;
                float v1 = C[mt][nt][hlf*2 + 1] + vb;
                const float s0 = v0*v0, s1 = v1*v1;
                if (OUT_XT) {
                    const __nv_bfloat16 h0 = __float2bfloat16(s0);
                    const __nv_bfloat16 h1 = __float2bfloat16(s1);
                    const __nv_bfloat16 l0 = __float2bfloat16(s0 - __bfloat162float(h0));
                    const __nv_bfloat16 l1 = __float2bfloat16(s1 - __bfloat162float(h1));
                    const size_t o = (((size_t)co*HH + (oh + PAD))*WP + (ow + PAD))*64 + n;
                    *(uint32_t*)(oxh + o) = pack_bf(h0, h1);
                    *(uint32_t*)(oxl + o) = pack_bf(l0, l1);
                } else {
                    const size_t o = (((size_t)co*H + oh)*H + ow)*64 + n;
                    *(float2*)(ofp + o) = make_float2(s0, s1);
                }
            }
        }
    }
}

// ---------------- weight prep -> swizzled [128x32] A tiles ----------------
__global__ void prep_w(const float* __restrict__ w, __nv_bfloat16* __restrict__ dh,
                       __nv_bfloat16* __restrict__ dl, int CIN, int KS2, int CB, int NKB, int total)
{
    int idx = blockIdx.x * blockDim.x + threadIdx.x;
    if (idx >= total) return;
    const int e = idx & 4095;
    const int kb = (idx >> 12) % NKB;
    const int cotile = idx / (NKB * 4096);
    const int co = e >> 5, kk = e & 31;
    const int tap = kb / CB;
    const int ci = (kb % CB)*32 + kk;
    const float val = w[((size_t)(cotile*128 + co)*CIN + ci)*KS2 + tap];
    const __nv_bfloat16 hv = __float2bfloat16(val);
    const __nv_bfloat16 lv = __float2bfloat16(val - __bfloat162float(hv));
    const size_t o = ((size_t)(cotile*NKB + kb) << 12) + co*32 + (kk ^ ((co & 3) << 3));
    dh[o] = hv; dl[o] = lv;
}

// ---------------- NCHW fp32 -> CHWN split-bf16 halo2 [96][31][32][64] ----------------
__global__ __launch_bounds__(128) void to_chwn27(
    const float* __restrict__ x, __nv_bfloat16* __restrict__ dh, __nv_bfloat16* __restrict__ dl)
{
    __shared__ float s[27][64];
    const int ci = blockIdx.y;
    const int ih = blockIdx.x;
    const int tid = threadIdx.x;
    for (int i = tid; i < 27*64; i += 128) {
        const int n = i / 27, iw = i % 27;
        s[iw][n] = x[(((size_t)n*96 + ci)*27 + ih)*27 + iw];
    }
    __syncthreads();
    for (int i = tid; i < 27*64; i += 128) {
        const int iw = i >> 6, n = i & 63;
        const float v = s[iw][n];
        const __nv_bfloat16 hv = __float2bfloat16(v);
        const __nv_bfloat16 lv = __float2bfloat16(v - __bfloat162float(hv));
        const size_t o = (((size_t)ci*31 + ih + 2)*32 + iw + 2)*64 + n;
        dh[o] = hv; dl[o] = lv;
    }
}

// ---------------- pool2: CHWN fp32 27x27 -> CHWN split-bf16 halo1 ----------------
__global__ void pool2_chwn(const float* __restrict__ x, __nv_bfloat16* __restrict__ dh,
                           __nv_bfloat16* __restrict__ dl, int total)
{
    int idx = blockIdx.x * blockDim.x + threadIdx.x;
    if (idx >= total) return;
    const int n = idx & 63;
    int r = idx >> 6;
    const int ow = r % 13; r /= 13;
    const int oh = r % 13; r /= 13;
    const int co = r;
    float s = 0.f;
    #pragma unroll
    for (int i = 0; i < 3; ++i)
        #pragma unroll
        for (int j = 0; j < 3; ++j)
            s += x[(((size_t)co*27 + (oh*2 + i))*27 + (ow*2 + j))*64 + n];
    const float v = s * (1.0f/9.0f);
    const __nv_bfloat16 hv = __float2bfloat16(v);
    const __nv_bfloat16 lv = __float2bfloat16(v - __bfloat162float(hv));
    const size_t o = (((size_t)co*15 + oh + 1)*16 + ow + 1)*64 + n;
    dh[o] = hv; dl[o] = lv;
}

// ---------------- pool3: CHWN fp32 -> NCHW flatten ----------------
__global__ void pool3_chwn(const float* __restrict__ x, float* __restrict__ y, int total)
{
    int idx = blockIdx.x * blockDim.x + threadIdx.x;
    if (idx >= total) return;
    const int n = idx & 63;
    int r = idx >> 6;
    const int ow = r % 6; r /= 6;
    const int oh = r % 6; r /= 6;
    const int co = r;
    float s = 0.f;
    #pragma unroll
    for (int i = 0; i < 3; ++i)
        #pragma unroll
        for (int j = 0; j < 3; ++j)
            s += x[(((size_t)co*13 + (oh*2 + i))*13 + (ow*2 + j))*64 + n];
    y[(size_t)n*9216 + co*36 + oh*6 + ow] = s * (1.0f/9.0f);
}

// ================= conv1 (fp32) =================
__global__ __launch_bounds__(112) void conv1_v2(
    const float* __restrict__ x, const float* __restrict__ w,
    const float* __restrict__ b, float* __restrict__ y)
{
    __shared__ __align__(16) float xs[4][15][58];
    __shared__ __align__(16) float ws[32][121];
    const int tx = threadIdx.x, ty = threadIdx.y;
    const int tid = ty*28 + tx;
    const int blk = blockIdx.x;
    const int co0 = blockIdx.y * 32;
    const int n   = blockIdx.z;
    const int ih0 = blk * 8;

    for (int i = tid; i < 4*15*58; i += 112) ((float*)xs)[i] = 0.f;

    float acc[2][2][8];
    #pragma unroll
    for (int o = 0; o < 2; ++o)
        #pragma unroll
        for (int j = 0; j < 2; ++j)
            #pragma unroll
            for (int cc = 0; cc < 8; ++cc) acc[o][j][cc] = 0.f;

    const float* xn = x + (size_t)n * (3*227*227);
    for (int c = 0; c < 3; ++c) {
        __syncthreads();
        for (int i = tid; i < 32*121; i += 112) {
            int ci = i / 121, k = i % 121;
            ws[ci][k] = w[(size_t)(co0+ci)*363 + c*121 + k];
        }
        for (int i = tid; i < 15*227; i += 112) {
            int r = i / 227, iw = i % 227;
            int ih = ih0 + r;
            xs[iw & 3][r][iw >> 2] = (ih < 227) ? xn[((size_t)c*227 + ih)*227 + iw] : 0.f;
        }
        __syncthreads();
        #pragma unroll
        for (int kh = 0; kh < 11; ++kh) {
            #pragma unroll
            for (int kw = 0; kw < 11; ++kw) {
                const int kr = kw & 3, kq = kw >> 2;
                const float x00 = xs[kr][kh][tx + kq];
                const float x01 = xs[kr][kh][tx + 28 + kq];
                const float x10 = xs[kr][kh + 4][tx + kq];
                const float x11 = xs[kr][kh + 4][tx + 28 + kq];
                #pragma unroll
                for (int cc = 0; cc < 8; ++cc) {
                    const float wv = ws[ty*8 + cc][kh*11 + kw];
                    acc[0][0][cc] += wv * x00;
                    acc[0][1][cc] += wv * x01;
                    acc[1][0][cc] += wv * x10;
                    acc[1][1][cc] += wv * x11;
                }
            }
        }
    }
    #pragma unroll
    for (int cc = 0; cc < 8; ++cc) {
        const int co = co0 + ty*8 + cc;
        const float vb = b[co] + 1.0f;
        #pragma unroll
        for (int o = 0; o < 2; ++o) {
            const int oh = blk*2 + o;
            if (oh >= 55) continue;
            #pragma unroll
            for (int j = 0; j < 2; ++j) {
                const int ow = tx + 28*j;
                if (ow >= 55) continue;
                float v = acc[o][j][cc] + vb;
                y[(((size_t)n*96 + co)*55 + oh)*55 + ow] = v*v;
            }
        }
    }
}

// ---------------- 3x3 s2 avg pool (NCHW) ----------------
__global__ void avgpool_kernel(const float* __restrict__ x, float* __restrict__ y,
                               int H, int OH, int total)
{
    int idx = blockIdx.x*blockDim.x + threadIdx.x;
    if (idx >= total) return;
    int ow = idx % OH; int t = idx / OH;
    int oh = t % OH;   t /= OH;
    const float* xp = x + ((size_t)t*H + oh*2)*H + ow*2;
    float s = 0.f;
    #pragma unroll
    for (int i = 0; i < 3; ++i)
        #pragma unroll
        for (int j = 0; j < 3; ++j) s += xp[i*H + j];
    y[idx] = s * (1.0f/9.0f);
}

// ---------------- FC: all 64 rows per thread, f32x2, K-split ----------------
__global__ __launch_bounds__(128) void fc_big(
    const float* __restrict__ x, const float* __restrict__ w,
    float* __restrict__ part, int K, int N, int S)
{
    const int n = blockIdx.x*128 + threadIdx.x;
    const int s = blockIdx.z;
    const int kc = K / S;
    const int k0 = s*kc, k1 = k0 + kc;
    const int tid = threadIdx.x;

    __shared__ __align__(16) float xs[32][66];   // [k][m], pad 66 keeps 8B alignment
    unsigned long long acc2[32];
    #pragma unroll
    for (int i = 0; i < 32; ++i) acc2[i] = 0ull;

    for (int kt = k0; kt < k1; kt += 32) {
        __syncthreads();
        for (int i = tid; i < 2048; i += 128) {
            const int kk = i & 31, m = i >> 5;
            xs[kk][m] = x[(size_t)m*K + kt + kk];
        }
        __syncthreads();
        if (n < N) {
            #pragma unroll 4
            for (int kk = 0; kk < 32; ++kk) {
                const float wv = w[(size_t)(kt + kk)*N + n];
                const unsigned long long wp = pk2(wv, wv);
                #pragma unroll
                for (int mp = 0; mp < 32; ++mp)
                    fma2(acc2[mp], *(const unsigned long long*)&xs[kk][2*mp], wp);
            }
        }
    }
    if (n < N) {
        #pragma unroll
        for (int mp = 0; mp < 32; ++mp) {
            float v0, v1;
            upk2(v0, v1, acc2[mp]);
            part[((size_t)s*64 + 2*mp    )*N + n] = v0;
            part[((size_t)s*64 + 2*mp + 1)*N + n] = v1;
        }
    }
}

__global__ void fc_reduce(const float* __restrict__ part, const float* __restrict__ bias,
                          float* __restrict__ out, int N, int S, int total)
{
    int idx = blockIdx.x*blockDim.x + threadIdx.x;
    if (idx >= total) return;
    int n = idx % N;
    float s = bias[n];
    for (int i = 0; i < S; ++i) s += part[(size_t)i*64*N + idx];
    out[idx] = s;
}

// ---------------- host launcher ----------------
extern "C" void kernel_launch(void* const* d_in, const int* in_sizes, int n_in,
                              void* d_out, int out_size)
{
    const float* x   = (const float*)d_in[0];
    const float* w1  = (const float*)d_in[1];
    const float* b1  = (const float*)d_in[2];
    const float* w2  = (const float*)d_in[3];
    const float* b2  = (const float*)d_in[4];
    const float* w3  = (const float*)d_in[5];
    const float* b3  = (const float*)d_in[6];
    const float* w4  = (const float*)d_in[7];
    const float* b4  = (const float*)d_in[8];
    const float* w5  = (const float*)d_in[9];
    const float* b5  = (const float*)d_in[10];
    const float* fw1 = (const float*)d_in[11];
    const float* fb1 = (const float*)d_in[12];
    const float* fw2 = (const float*)d_in[13];
    const float* fb2 = (const float*)d_in[14];
    const float* fw3 = (const float*)d_in[15];
    const float* fb3 = (const float*)d_in[16];
    float* out = (float*)d_out;

    float *a1,*p1,*a2t,*a5t,*p3,*f1,*f2,*part;
    __nv_bfloat16 *xt2h,*xt2l,*xt3h,*xt3l,*xt4h,*xt4l,*xt5h,*xt5l;
    __nv_bfloat16 *w2h,*w2l,*w3h,*w3l,*w4h,*w4l,*w5h,*w5l;
    cudaGetSymbolAddress((void**)&a1, g_a1);
    cudaGetSymbolAddress((void**)&p1, g_p1);
    cudaGetSymbolAddress((void**)&a2t, g_a2t);
    cudaGetSymbolAddress((void**)&a5t, g_a5t);
    cudaGetSymbolAddress((void**)&p3, g_p3);
    cudaGetSymbolAddress((void**)&f1, g_f1);
    cudaGetSymbolAddress((void**)&f2, g_f2);
    cudaGetSymbolAddress((void**)&part, g_part);
    cudaGetSymbolAddress((void**)&xt2h, g_xt2h);
    cudaGetSymbolAddress((void**)&xt2l, g_xt2l);
    cudaGetSymbolAddress((void**)&xt3h, g_xt3h);
    cudaGetSymbolAddress((void**)&xt3l, g_xt3l);
    cudaGetSymbolAddress((void**)&xt4h, g_xt4h);
    cudaGetSymbolAddress((void**)&xt4l, g_xt4l);
    cudaGetSymbolAddress((void**)&xt5h, g_xt5h);
    cudaGetSymbolAddress((void**)&xt5l, g_xt5l);
    cudaGetSymbolAddress((void**)&w2h, g_w2h);
    cudaGetSymbolAddress((void**)&w2l, g_w2l);
    cudaGetSymbolAddress((void**)&w3h, g_w3h);
    cudaGetSymbolAddress((void**)&w3l, g_w3l);
    cudaGetSymbolAddress((void**)&w4h, g_w4h);
    cudaGetSymbolAddress((void**)&w4l, g_w4l);
    cudaGetSymbolAddress((void**)&w5h, g_w5h);
    cudaGetSymbolAddress((void**)&w5l, g_w5l);

    cudaFuncSetAttribute(mconv2<96,5,27,2,0>,  cudaFuncAttributeMaxDynamicSharedMemorySize, 65536);
    cudaFuncSetAttribute(mconv2<256,3,13,1,1>, cudaFuncAttributeMaxDynamicSharedMemorySize, 65536);
    cudaFuncSetAttribute(mconv2<384,3,13,1,1>, cudaFuncAttributeMaxDynamicSharedMemorySize, 65536);
    cudaFuncSetAttribute(mconv2<384,3,13,1,0>, cudaFuncAttributeMaxDynamicSharedMemorySize, 65536);

    // zero halo'd activation tensors
    cudaMemsetAsync(xt2h, 0, sizeof(g_xt2h));
    cudaMemsetAsync(xt2l, 0, sizeof(g_xt2l));
    cudaMemsetAsync(xt3h, 0, sizeof(g_xt3h));
    cudaMemsetAsync(xt3l, 0, sizeof(g_xt3l));
    cudaMemsetAsync(xt4h, 0, sizeof(g_xt4h));
    cudaMemsetAsync(xt4l, 0, sizeof(g_xt4l));
    cudaMemsetAsync(xt5h, 0, sizeof(g_xt5h));
    cudaMemsetAsync(xt5l, 0, sizeof(g_xt5l));

    // weight prep
    { int tot = 2*75*4096;  prep_w<<<(tot+255)/256, 256>>>(w2, w2h, w2l,  96, 25,  3,  75, tot); }
    { int tot = 3*72*4096;  prep_w<<<(tot+255)/256, 256>>>(w3, w3h, w3l, 256,  9,  8,  72, tot); }
    { int tot = 3*108*4096; prep_w<<<(tot+255)/256, 256>>>(w4, w4h, w4l, 384,  9, 12, 108, tot); }
    { int tot = 2*108*4096; prep_w<<<(tot+255)/256, 256>>>(w5, w5h, w5l, 384,  9, 12, 108, tot); }

    // conv1 + pool1 (fp32 NCHW)
    conv1_v2<<<dim3(28, 3, 64), dim3(28, 4)>>>(x, w1, b1, a1);
    { int t = 64*96*27*27; avgpool_kernel<<<(t+255)/256, 256>>>(a1, p1, 55, 27, t); }
    // convert to CHWN split-bf16 halo2
    to_chwn27<<<dim3(27, 96), 128>>>(p1, xt2h, xt2l);
    // conv2 (mma) -> fp32 CHWN
    mconv2<96,5,27,2,0><<<dim3(27*14, 2), 256, 65536>>>(xt2h, xt2l, w2h, w2l, b2, nullptr, nullptr, a2t);
    // pool2 -> CHWN split-bf16 halo1
    { int t = 256*13*13*64; pool2_chwn<<<(t+255)/256, 256>>>(a2t, xt3h, xt3l, t); }
    // conv3/4/5 (mma)
    mconv2<256,3,13,1,1><<<dim3(13*7, 3), 256, 65536>>>(xt3h, xt3l, w3h, w3l, b3, xt4h, xt4l, nullptr);
    mconv2<384,3,13,1,1><<<dim3(13*7, 3), 256, 65536>>>(xt4h, xt4l, w4h, w4l, b4, xt5h, xt5l, nullptr);
    mconv2<384,3,13,1,0><<<dim3(13*7, 2), 256, 65536>>>(xt5h, xt5l, w5h, w5l, b5, nullptr, nullptr, a5t);
    // pool3 -> NCHW flatten
    { int t = 64*256*36; pool3_chwn<<<(t+255)/256, 256>>>(a5t, p3, t); }

    // FC (K-split 8, weights read once)
    fc_big<<<dim3(32, 1, 8), 128>>>(p3, fw1, part, 9216, 4096, 8);
    fc_reduce<<<(64*4096 + 255)/256, 256>>>(part, fb1, f1, 4096, 8, 64*4096);
    fc_big<<<dim3(32, 1, 8), 128>>>(f1, fw2, part, 4096, 4096, 8);
    fc_reduce<<<(64*4096 + 255)/256, 256>>>(part, fb2, f2, 4096, 8, 64*4096);
    fc_big<<<dim3(8, 1, 8), 128>>>(f2, fw3, part, 4096, 1000, 8);
    fc_reduce<<<(64*1000 + 255)/256, 256>>>(part, fb3, out, 1000, 8, 64*1000);
}

// round 10
// speedup vs baseline: 8.2728x; 1.2360x over previous
#include <cuda_runtime.h>
#include <cuda_bf16.h>
#include <cstddef>
#include <cstdint>

// ---------------- scratch ----------------
__device__ __align__(16) float g_a1t[96*55*55*64];    // conv1 out CHWN fp32
__device__ __align__(16) float g_a2t[256*27*27*64];   // conv2 out CHWN fp32
__device__ __align__(16) float g_a5t[256*13*13*64];   // conv5 out CHWN fp32
__device__ __align__(16) float g_p3[64*256*6*6];
__device__ __align__(16) float g_f1[64*4096];
__device__ __align__(16) float g_f2[64*4096];
__device__ __align__(16) float g_part[8*64*4096];
__device__ __align__(16) __nv_bfloat16 g_zero[64];    // finite pad rows for conv1 B

// CHWN split-bf16 activations
__device__ __align__(16) __nv_bfloat16 g_xc1h[3*227*227*64];
__device__ __align__(16) __nv_bfloat16 g_xc1l[3*227*227*64];
__device__ __align__(16) __nv_bfloat16 g_xt2h[96*31*32*64];
__device__ __align__(16) __nv_bfloat16 g_xt2l[96*31*32*64];
__device__ __align__(16) __nv_bfloat16 g_xt3h[256*15*16*64];
__device__ __align__(16) __nv_bfloat16 g_xt3l[256*15*16*64];
__device__ __align__(16) __nv_bfloat16 g_xt4h[384*15*16*64];
__device__ __align__(16) __nv_bfloat16 g_xt4l[384*15*16*64];
__device__ __align__(16) __nv_bfloat16 g_xt5h[384*15*16*64];
__device__ __align__(16) __nv_bfloat16 g_xt5l[384*15*16*64];
// pre-packed swizzled weight A-tiles: [cotile][kblk][128co x 32k]
__device__ __align__(16) __nv_bfloat16 g_w1h[12*4096];
__device__ __align__(16) __nv_bfloat16 g_w1l[12*4096];
__device__ __align__(16) __nv_bfloat16 g_w2h[2*75*4096];
__device__ __align__(16) __nv_bfloat16 g_w2l[2*75*4096];
__device__ __align__(16) __nv_bfloat16 g_w3h[3*72*4096];
__device__ __align__(16) __nv_bfloat16 g_w3l[3*72*4096];
__device__ __align__(16) __nv_bfloat16 g_w4h[3*108*4096];
__device__ __align__(16) __nv_bfloat16 g_w4l[3*108*4096];
__device__ __align__(16) __nv_bfloat16 g_w5h[2*108*4096];
__device__ __align__(16) __nv_bfloat16 g_w5l[2*108*4096];

// ---------------- helpers ----------------
__device__ __forceinline__ uint32_t smem_u32(const void* p) {
    uint32_t a; asm("{ .reg .u64 t; cvta.to.shared.u64 t, %1; cvt.u32.u64 %0, t; }" : "=r"(a) : "l"(p)); return a;
}
__device__ __forceinline__ void mma_bf16(float* c, const unsigned* a, const unsigned* b) {
    asm volatile("mma.sync.aligned.m16n8k16.row.col.f32.bf16.bf16.f32 "
        "{%0,%1,%2,%3}, {%4,%5,%6,%7}, {%8,%9}, {%0,%1,%2,%3};"
        : "+f"(c[0]), "+f"(c[1]), "+f"(c[2]), "+f"(c[3])
        : "r"(a[0]), "r"(a[1]), "r"(a[2]), "r"(a[3]), "r"(b[0]), "r"(b[1]));
}
__device__ __forceinline__ void ldsm_x4(unsigned* r, uint32_t addr) {
    asm volatile("ldmatrix.sync.aligned.m8n8.x4.shared.b16 {%0,%1,%2,%3}, [%4];"
        : "=r"(r[0]), "=r"(r[1]), "=r"(r[2]), "=r"(r[3]) : "r"(addr));
}
__device__ __forceinline__ void ldsm_x2t(unsigned* r, uint32_t addr) {
    asm volatile("ldmatrix.sync.aligned.m8n8.x2.trans.shared.b16 {%0,%1}, [%2];"
        : "=r"(r[0]), "=r"(r[1]) : "r"(addr));
}
__device__ __forceinline__ uint32_t pack_bf(__nv_bfloat16 lo, __nv_bfloat16 hi) {
    return ((uint32_t)__bfloat16_as_ushort(hi) << 16) | __bfloat16_as_ushort(lo);
}
__device__ __forceinline__ void cp_async16(uint32_t dst, const void* src) {
    asm volatile("cp.async.cg.shared.global [%0], [%1], 16;" :: "r"(dst), "l"(src));
}
#define CP_COMMIT() asm volatile("cp.async.commit_group;" ::: "memory")
#define CP_WAIT0()  asm volatile("cp.async.wait_group 0;" ::: "memory")
__device__ __forceinline__ void fma2(unsigned long long &acc, unsigned long long a, unsigned long long b) {
    asm("fma.rn.f32x2 %0, %1, %2, %0;" : "+l"(acc) : "l"(a), "l"(b));
}
__device__ __forceinline__ unsigned long long pk2(float lo, float hi) {
    unsigned long long r; asm("mov.b64 %0, {%1, %2};" : "=l"(r) : "f"(lo), "f"(hi)); return r;
}
__device__ __forceinline__ void upk2(float &lo, float &hi, unsigned long long v) {
    asm("mov.b64 {%0, %1}, %2;" : "=f"(lo), "=f"(hi) : "l"(v));
}

// ================= mma conv v2 (stride-1 layers): 2 pixels/CTA, double-buffered =================
template<int CIN, int KS, int H, int PAD, int OUT_XT>
__global__ __launch_bounds__(256) void mconv2(
    const __nv_bfloat16* __restrict__ xh, const __nv_bfloat16* __restrict__ xl,
    const __nv_bfloat16* __restrict__ wh, const __nv_bfloat16* __restrict__ wl,
    const float* __restrict__ bias,
    __nv_bfloat16* __restrict__ oxh, __nv_bfloat16* __restrict__ oxl,
    float* __restrict__ ofp)
{
    extern __shared__ __align__(16) char smem[];
    constexpr int HH = H + 2*PAD;
    constexpr int WP = ((HH + 15)/16)*16;
    constexpr int CB = CIN/32;
    constexpr int NKB = KS*KS*CB;
    constexpr int OWP = (H + 1)/2;

    const int tid = threadIdx.x;
    const int warp = tid >> 5, lane = tid & 31;
    const int wm = warp & 3, wn = warp >> 2;
    const int bx = blockIdx.x;
    const int oh = bx / OWP, ow0 = (bx % OWP)*2;
    const int npx = (ow0 + 1 < H) ? 2 : 1;
    const int cotile = blockIdx.y;
    const uint32_t sb = smem_u32(smem);

    const int sr = tid >> 3, su = tid & 7;
    const uint32_t brow = sr*128 + ((su*16) ^ ((sr & 7) << 4));

    auto stage = [&](int kb, int bb) {
        const uint32_t base = sb + bb*32768;
        const size_t wbase16 = ((size_t)(cotile*NKB + kb)) << 13;
        #pragma unroll
        for (int j = 0; j < 2; ++j) {
            const int c = tid + j*256;
            cp_async16(base + c*16,        (const char*)wh + wbase16 + c*16);
            cp_async16(base + 8192 + c*16, (const char*)wl + wbase16 + c*16);
        }
        const int tap = kb / CB, ci0 = (kb % CB)*32;
        const int kh = tap / KS, kw = tap % KS;
        #pragma unroll
        for (int p = 0; p < 2; ++p) {
            const int ow = (p < npx) ? (ow0 + p) : ow0;
            const size_t src = (((size_t)(ci0 + sr)*HH + oh + kh)*WP + ow + kw)*64 + su*8;
            cp_async16(base + 16384 + p*4096 + brow, xh + src);
            cp_async16(base + 24576 + p*4096 + brow, xl + src);
        }
    };

    float C[2][8][4];
    #pragma unroll
    for (int a = 0; a < 2; ++a)
        #pragma unroll
        for (int b = 0; b < 8; ++b)
            #pragma unroll
            for (int c = 0; c < 4; ++c) C[a][b][c] = 0.f;

    stage(0, 0); CP_COMMIT();
    int cur = 0;

    for (int kb = 0; kb < NKB; ++kb) {
        CP_WAIT0();
        __syncthreads();
        if (kb + 1 < NKB) { stage(kb + 1, cur ^ 1); CP_COMMIT(); }

        const uint32_t bA = sb + cur*32768;
        const uint32_t bB = bA + 16384 + wn*4096;
        const int q = lane >> 3, rr = lane & 7;
        #pragma unroll
        for (int kc = 0; kc < 2; ++kc) {
            unsigned ah[2][4], al[2][4];
            #pragma unroll
            for (int mt = 0; mt < 2; ++mt) {
                const int row = wm*32 + mt*16 + (q & 1)*8 + rr;
                const uint32_t off = row*64 + ((kc*32 + (q >> 1)*16) ^ ((row & 3) << 4));
                ldsm_x4(ah[mt], bA + off);
                ldsm_x4(al[mt], bA + 8192 + off);
            }
            const int k = kc*16 + (lane & 15);
            #pragma unroll
            for (int nt = 0; nt < 8; ++nt) {
                unsigned bh[2], bl[2];
                const uint32_t off = k*128 + ((nt*16) ^ ((k & 7) << 4));
                ldsm_x2t(bh, bB + off);
                ldsm_x2t(bl, bB + 8192 + off);
                #pragma unroll
                for (int mt = 0; mt < 2; ++mt) {
                    mma_bf16(C[mt][nt], ah[mt], bh);
                    mma_bf16(C[mt][nt], ah[mt], bl);
                    mma_bf16(C[mt][nt], al[mt], bh);
                }
            }
        }
        cur ^= 1;
    }

    const int p = wn;
    if (p >= npx) return;
    const int ow = ow0 + p;
    const int g = lane >> 2, tg = lane & 3;
    #pragma unroll
    for (int mt = 0; mt < 2; ++mt) {
        #pragma unroll
        for (int hlf = 0; hlf < 2; ++hlf) {
            const int co = cotile*128 + wm*32 + mt*16 + hlf*8 + g;
            const float vb = bias[co] + 1.0f;
            #pragma unroll
            for (int nt = 0; nt < 8; ++nt) {
                const int n = nt*8 + tg*2;
                float v0 = C[mt][nt][hlf*2 + 0] + vb;
                float v1 = C[mt][nt][hlf*2 + 1] + vb;
                const float s0 = v0*v0, s1 = v1*v1;
                if (OUT_XT) {
                    const __nv_bfloat16 h0 = __float2bfloat16(s0);
                    const __nv_bfloat16 h1 = __float2bfloat16(s1);
                    const __nv_bfloat16 l0 = __float2bfloat16(s0 - __bfloat162float(h0));
                    const __nv_bfloat16 l1 = __float2bfloat16(s1 - __bfloat162float(h1));
                    const size_t o = (((size_t)co*HH + (oh + PAD))*WP + (ow + PAD))*64 + n;
                    *(uint32_t*)(oxh + o) = pack_bf(h0, h1);
                    *(uint32_t*)(oxl + o) = pack_bf(l0, l1);
                } else {
                    const size_t o = (((size_t)co*H + oh)*H + ow)*64 + n;
                    *(float2*)(ofp + o) = make_float2(s0, s1);
                }
            }
        }
    }
}

// ================= mma conv1: k11 s4, 227 -> 55x55, K=363 pad 384, 96(+32 pad) co =================
__global__ __launch_bounds__(256) void mconv1(
    const __nv_bfloat16* __restrict__ xh, const __nv_bfloat16* __restrict__ xl,
    const __nv_bfloat16* __restrict__ wh, const __nv_bfloat16* __restrict__ wl,
    const float* __restrict__ bias, const __nv_bfloat16* __restrict__ zbuf,
    float* __restrict__ ofp)
{
    extern __shared__ __align__(16) char smem[];
    constexpr int NKB = 12;

    const int tid = threadIdx.x;
    const int warp = tid >> 5, lane = tid & 31;
    const int wm = warp & 3, wn = warp >> 2;
    const int bx = blockIdx.x;
    const int oh = bx / 28, ow0 = (bx % 28)*2;
    const int npx = (ow0 + 1 < 55) ? 2 : 1;
    const uint32_t sb = smem_u32(smem);

    const int sr = tid >> 3, su = tid & 7;
    const uint32_t brow = sr*128 + ((su*16) ^ ((sr & 7) << 4));

    auto stage = [&](int kb, int bb) {
        const uint32_t base = sb + bb*32768;
        const size_t wbase16 = ((size_t)kb) << 13;
        #pragma unroll
        for (int j = 0; j < 2; ++j) {
            const int c = tid + j*256;
            cp_async16(base + c*16,        (const char*)wh + wbase16 + c*16);
            cp_async16(base + 8192 + c*16, (const char*)wl + wbase16 + c*16);
        }
        const int k = kb*32 + sr;
        const bool valid = k < 363;
        const int tap = k/3, ci = k%3;
        const int kh = tap/11, kw = tap%11;
        #pragma unroll
        for (int p = 0; p < 2; ++p) {
            const int ow = (p < npx) ? (ow0 + p) : ow0;
            const __nv_bfloat16* sh;
            const __nv_bfloat16* sl;
            if (valid) {
                const size_t src = (((size_t)ci*227 + oh*4 + kh)*227 + ow*4 + kw)*64 + su*8;
                sh = xh + src; sl = xl + src;
            } else { sh = zbuf + su*8; sl = zbuf + su*8; }
            cp_async16(base + 16384 + p*4096 + brow, sh);
            cp_async16(base + 24576 + p*4096 + brow, sl);
        }
    };

    float C[2][8][4];
    #pragma unroll
    for (int a = 0; a < 2; ++a)
        #pragma unroll
        for (int b = 0; b < 8; ++b)
            #pragma unroll
            for (int c = 0; c < 4; ++c) C[a][b][c] = 0.f;

    stage(0, 0); CP_COMMIT();
    int cur = 0;

    for (int kb = 0; kb < NKB; ++kb) {
        CP_WAIT0();
        __syncthreads();
        if (kb + 1 < NKB) { stage(kb + 1, cur ^ 1); CP_COMMIT(); }

        const uint32_t bA = sb + cur*32768;
        const uint32_t bB = bA + 16384 + wn*4096;
        const int q = lane >> 3, rr = lane & 7;
        #pragma unroll
        for (int kc = 0; kc < 2; ++kc) {
            unsigned ah[2][4], al[2][4];
            #pragma unroll
            for (int mt = 0; mt < 2; ++mt) {
                const int row = wm*32 + mt*16 + (q & 1)*8 + rr;
                const uint32_t off = row*64 + ((kc*32 + (q >> 1)*16) ^ ((row & 3) << 4));
                ldsm_x4(ah[mt], bA + off);
                ldsm_x4(al[mt], bA + 8192 + off);
            }
            const int k = kc*16 + (lane & 15);
            #pragma unroll
            for (int nt = 0; nt < 8; ++nt) {
                unsigned bh[2], bl[2];
                const uint32_t off = k*128 + ((nt*16) ^ ((k & 7) << 4));
                ldsm_x2t(bh, bB + off);
                ldsm_x2t(bl, bB + 8192 + off);
                #pragma unroll
                for (int mt = 0; mt < 2; ++mt) {
                    mma_bf16(C[mt][nt], ah[mt], bh);
                    mma_bf16(C[mt][nt], ah[mt], bl);
                    mma_bf16(C[mt][nt], al[mt], bh);
                }
            }
        }
        cur ^= 1;
    }

    const int p = wn;
    if (p >= npx) return;
    const int ow = ow0 + p;
    const int g = lane >> 2, tg = lane & 3;
    #pragma unroll
    for (int mt = 0; mt < 2; ++mt) {
        #pragma unroll
        for (int hlf = 0; hlf < 2; ++hlf) {
            const int co = wm*32 + mt*16 + hlf*8 + g;
            if (co >= 96) continue;
            const float vb = bias[co] + 1.0f;
            #pragma unroll
            for (int nt = 0; nt < 8; ++nt) {
                const int n = nt*8 + tg*2;
                float v0 = C[mt][nt][hlf*2 + 0] + vb;
                float v1 = C[mt][nt][hlf*2 + 1] + vb;
                const size_t o = (((size_t)co*55 + oh)*55 + ow)*64 + n;
                *(float2*)(ofp + o) = make_float2(v0*v0, v1*v1);
            }
        }
    }
}

// ---------------- weight prep (generic conv2..5) ----------------
__global__ void prep_w(const float* __restrict__ w, __nv_bfloat16* __restrict__ dh,
                       __nv_bfloat16* __restrict__ dl, int CIN, int KS2, int CB, int NKB, int total)
{
    int idx = blockIdx.x * blockDim.x + threadIdx.x;
    if (idx >= total) return;
    const int e = idx & 4095;
    const int kb = (idx >> 12) % NKB;
    const int cotile = idx / (NKB * 4096);
    const int co = e >> 5, kk = e & 31;
    const int tap = kb / CB;
    const int ci = (kb % CB)*32 + kk;
    const float val = w[((size_t)(cotile*128 + co)*CIN + ci)*KS2 + tap];
    const __nv_bfloat16 hv = __float2bfloat16(val);
    const __nv_bfloat16 lv = __float2bfloat16(val - __bfloat162float(hv));
    const size_t o = ((size_t)(cotile*NKB + kb) << 12) + co*32 + (kk ^ ((co & 3) << 3));
    dh[o] = hv; dl[o] = lv;
}

// ---------------- weight prep conv1: k = tap*3+ci, pad k>=363 / co>=96 ----------------
__global__ void prep_w1(const float* __restrict__ w, __nv_bfloat16* __restrict__ dh,
                        __nv_bfloat16* __restrict__ dl)
{
    int idx = blockIdx.x * blockDim.x + threadIdx.x;
    if (idx >= 12*4096) return;
    const int e = idx & 4095;
    const int kb = idx >> 12;
    const int co = e >> 5, kk = e & 31;
    const int k = kb*32 + kk;
    float val = 0.f;
    if (k < 363 && co < 96) {
        const int tap = k/3, ci = k%3;
        val = w[((size_t)(co*3 + ci)*11 + tap/11)*11 + tap%11];
    }
    const __nv_bfloat16 hv = __float2bfloat16(val);
    const __nv_bfloat16 lv = __float2bfloat16(val - __bfloat162float(hv));
    const size_t o = ((size_t)kb << 12) + co*32 + (kk ^ ((co & 3) << 3));
    dh[o] = hv; dl[o] = lv;
}

// ---------------- input NCHW fp32 -> CHWN split-bf16 [3][227][227][64] ----------------
__global__ __launch_bounds__(256) void to_chwn227(
    const float* __restrict__ x, __nv_bfloat16* __restrict__ dh, __nv_bfloat16* __restrict__ dl)
{
    extern __shared__ float s[];   // [227][65]
    const int ci = blockIdx.y;
    const int ih = blockIdx.x;
    const int tid = threadIdx.x;
    for (int i = tid; i < 227*64; i += 256) {
        const int n = i / 227, iw = i % 227;
        s[iw*65 + n] = x[(((size_t)n*3 + ci)*227 + ih)*227 + iw];
    }
    __syncthreads();
    for (int i = tid; i < 227*64; i += 256) {
        const int iw = i >> 6, n = i & 63;
        const float v = s[iw*65 + n];
        const __nv_bfloat16 hv = __float2bfloat16(v);
        const __nv_bfloat16 lv = __float2bfloat16(v - __bfloat162float(hv));
        const size_t o = (((size_t)ci*227 + ih)*227 + iw)*64 + n;
        dh[o] = hv; dl[o] = lv;
    }
}

// ---------------- pool1: CHWN fp32 55x55 -> CHWN split-bf16 halo2 [96][31][32][64] ----------------
__global__ void pool1_chwn(const float* __restrict__ x, __nv_bfloat16* __restrict__ dh,
                           __nv_bfloat16* __restrict__ dl, int total)
{
    int idx = blockIdx.x * blockDim.x + threadIdx.x;
    if (idx >= total) return;
    const int n = idx & 63;
    int r = idx >> 6;
    const int ow = r % 27; r /= 27;
    const int oh = r % 27; r /= 27;
    const int co = r;      // 0..95
    float s = 0.f;
    #pragma unroll
    for (int i = 0; i < 3; ++i)
        #pragma unroll
        for (int j = 0; j < 3; ++j)
            s += x[(((size_t)co*55 + (oh*2 + i))*55 + (ow*2 + j))*64 + n];
    const float v = s * (1.0f/9.0f);
    const __nv_bfloat16 hv = __float2bfloat16(v);
    const __nv_bfloat16 lv = __float2bfloat16(v - __bfloat162float(hv));
    const size_t o = (((size_t)co*31 + oh + 2)*32 + ow + 2)*64 + n;
    dh[o] = hv; dl[o] = lv;
}

// ---------------- pool2: CHWN fp32 27x27 -> CHWN split-bf16 halo1 ----------------
__global__ void pool2_chwn(const float* __restrict__ x, __nv_bfloat16* __restrict__ dh,
                           __nv_bfloat16* __restrict__ dl, int total)
{
    int idx = blockIdx.x * blockDim.x + threadIdx.x;
    if (idx >= total) return;
    const int n = idx & 63;
    int r = idx >> 6;
    const int ow = r % 13; r /= 13;
    const int oh = r % 13; r /= 13;
    const int co = r;
    float s = 0.f;
    #pragma unroll
    for (int i = 0; i < 3; ++i)
        #pragma unroll
        for (int j = 0; j < 3; ++j)
            s += x[(((size_t)co*27 + (oh*2 + i))*27 + (ow*2 + j))*64 + n];
    const float v = s * (1.0f/9.0f);
    const __nv_bfloat16 hv = __float2bfloat16(v);
    const __nv_bfloat16 lv = __float2bfloat16(v - __bfloat162float(hv));
    const size_t o = (((size_t)co*15 + oh + 1)*16 + ow + 1)*64 + n;
    dh[o] = hv; dl[o] = lv;
}

// ---------------- pool3: CHWN fp32 -> NCHW flatten ----------------
__global__ void pool3_chwn(const float* __restrict__ x, float* __restrict__ y, int total)
{
    int idx = blockIdx.x * blockDim.x + threadIdx.x;
    if (idx >= total) return;
    const int n = idx & 63;
    int r = idx >> 6;
    const int ow = r % 6; r /= 6;
    const int oh = r % 6; r /= 6;
    const int co = r;
    float s = 0.f;
    #pragma unroll
    for (int i = 0; i < 3; ++i)
        #pragma unroll
        for (int j = 0; j < 3; ++j)
            s += x[(((size_t)co*13 + (oh*2 + i))*13 + (ow*2 + j))*64 + n];
    y[(size_t)n*9216 + co*36 + oh*6 + ow] = s * (1.0f/9.0f);
}

// ---------------- FC: all 64 rows per thread, f32x2, K-split ----------------
__global__ __launch_bounds__(128) void fc_big(
    const float* __restrict__ x, const float* __restrict__ w,
    float* __restrict__ part, int K, int N, int S)
{
    const int n = blockIdx.x*128 + threadIdx.x;
    const int s = blockIdx.z;
    const int kc = K / S;
    const int k0 = s*kc, k1 = k0 + kc;
    const int tid = threadIdx.x;

    __shared__ __align__(16) float xs[32][66];
    unsigned long long acc2[32];
    #pragma unroll
    for (int i = 0; i < 32; ++i) acc2[i] = 0ull;

    for (int kt = k0; kt < k1; kt += 32) {
        __syncthreads();
        for (int i = tid; i < 2048; i += 128) {
            const int kk = i & 31, m = i >> 5;
            xs[kk][m] = x[(size_t)m*K + kt + kk];
        }
        __syncthreads();
        if (n < N) {
            #pragma unroll 4
            for (int kk = 0; kk < 32; ++kk) {
                const float wv = w[(size_t)(kt + kk)*N + n];
                const unsigned long long wp = pk2(wv, wv);
                #pragma unroll
                for (int mp = 0; mp < 32; ++mp)
                    fma2(acc2[mp], *(const unsigned long long*)&xs[kk][2*mp], wp);
            }
        }
    }
    if (n < N) {
        #pragma unroll
        for (int mp = 0; mp < 32; ++mp) {
            float v0, v1;
            upk2(v0, v1, acc2[mp]);
            part[((size_t)s*64 + 2*mp    )*N + n] = v0;
            part[((size_t)s*64 + 2*mp + 1)*N + n] = v1;
        }
    }
}

__global__ void fc_reduce(const float* __restrict__ part, const float* __restrict__ bias,
                          float* __restrict__ out, int N, int S, int total)
{
    int idx = blockIdx.x*blockDim.x + threadIdx.x;
    if (idx >= total) return;
    int n = idx % N;
    float s = bias[n];
    for (int i = 0; i < S; ++i) s += part[(size_t)i*64*N + idx];
    out[idx] = s;
}

// ---------------- host launcher ----------------
extern "C" void kernel_launch(void* const* d_in, const int* in_sizes, int n_in,
                              void* d_out, int out_size)
{
    const float* x   = (const float*)d_in[0];
    const float* w1  = (const float*)d_in[1];
    const float* b1  = (const float*)d_in[2];
    const float* w2  = (const float*)d_in[3];
    const float* b2  = (const float*)d_in[4];
    const float* w3  = (const float*)d_in[5];
    const float* b3  = (const float*)d_in[6];
    const float* w4  = (const float*)d_in[7];
    const float* b4  = (const float*)d_in[8];
    const float* w5  = (const float*)d_in[9];
    const float* b5  = (const float*)d_in[10];
    const float* fw1 = (const float*)d_in[11];
    const float* fb1 = (const float*)d_in[12];
    const float* fw2 = (const float*)d_in[13];
    const float* fb2 = (const float*)d_in[14];
    const float* fw3 = (const float*)d_in[15];
    const float* fb3 = (const float*)d_in[16];
    float* out = (float*)d_out;

    float *a1t,*a2t,*a5t,*p3,*f1,*f2,*part;
    __nv_bfloat16 *zb,*xc1h,*xc1l,*xt2h,*xt2l,*xt3h,*xt3l,*xt4h,*xt4l,*xt5h,*xt5l;
    __nv_bfloat16 *w1h,*w1l,*w2h,*w2l,*w3h,*w3l,*w4h,*w4l,*w5h,*w5l;
    cudaGetSymbolAddress((void**)&a1t, g_a1t);
    cudaGetSymbolAddress((void**)&a2t, g_a2t);
    cudaGetSymbolAddress((void**)&a5t, g_a5t);
    cudaGetSymbolAddress((void**)&p3, g_p3);
    cudaGetSymbolAddress((void**)&f1, g_f1);
    cudaGetSymbolAddress((void**)&f2, g_f2);
    cudaGetSymbolAddress((void**)&part, g_part);
    cudaGetSymbolAddress((void**)&zb, g_zero);
    cudaGetSymbolAddress((void**)&xc1h, g_xc1h);
    cudaGetSymbolAddress((void**)&xc1l, g_xc1l);
    cudaGetSymbolAddress((void**)&xt2h, g_xt2h);
    cudaGetSymbolAddress((void**)&xt2l, g_xt2l);
    cudaGetSymbolAddress((void**)&xt3h, g_xt3h);
    cudaGetSymbolAddress((void**)&xt3l, g_xt3l);
    cudaGetSymbolAddress((void**)&xt4h, g_xt4h);
    cudaGetSymbolAddress((void**)&xt4l, g_xt4l);
    cudaGetSymbolAddress((void**)&xt5h, g_xt5h);
    cudaGetSymbolAddress((void**)&xt5l, g_xt5l);
    cudaGetSymbolAddress((void**)&w1h, g_w1h);
    cudaGetSymbolAddress((void**)&w1l, g_w1l);
    cudaGetSymbolAddress((void**)&w2h, g_w2h);
    cudaGetSymbolAddress((void**)&w2l, g_w2l);
    cudaGetSymbolAddress((void**)&w3h, g_w3h);
    cudaGetSymbolAddress((void**)&w3l, g_w3l);
    cudaGetSymbolAddress((void**)&w4h, g_w4h);
    cudaGetSymbolAddress((void**)&w4l, g_w4l);
    cudaGetSymbolAddress((void**)&w5h, g_w5h);
    cudaGetSymbolAddress((void**)&w5l, g_w5l);

    cudaFuncSetAttribute(mconv1,               cudaFuncAttributeMaxDynamicSharedMemorySize, 65536);
    cudaFuncSetAttribute(mconv2<96,5,27,2,0>,  cudaFuncAttributeMaxDynamicSharedMemorySize, 65536);
    cudaFuncSetAttribute(mconv2<256,3,13,1,1>, cudaFuncAttributeMaxDynamicSharedMemorySize, 65536);
    cudaFuncSetAttribute(mconv2<384,3,13,1,1>, cudaFuncAttributeMaxDynamicSharedMemorySize, 65536);
    cudaFuncSetAttribute(mconv2<384,3,13,1,0>, cudaFuncAttributeMaxDynamicSharedMemorySize, 65536);
    cudaFuncSetAttribute(to_chwn227,           cudaFuncAttributeMaxDynamicSharedMemorySize, 227*65*4);

    cudaMemsetAsync(zb, 0, sizeof(g_zero));
    cudaMemsetAsync(xt2h, 0, sizeof(g_xt2h));
    cudaMemsetAsync(xt2l, 0, sizeof(g_xt2l));
    cudaMemsetAsync(xt3h, 0, sizeof(g_xt3h));
    cudaMemsetAsync(xt3l, 0, sizeof(g_xt3l));
    cudaMemsetAsync(xt4h, 0, sizeof(g_xt4h));
    cudaMemsetAsync(xt4l, 0, sizeof(g_xt4l));
    cudaMemsetAsync(xt5h, 0, sizeof(g_xt5h));
    cudaMemsetAsync(xt5l, 0, sizeof(g_xt5l));

    // weight prep
    prep_w1<<<(12*4096 + 255)/256, 256>>>(w1, w1h, w1l);
    { int tot = 2*75*4096;  prep_w<<<(tot+255)/256, 256>>>(w2, w2h, w2l,  96, 25,  3,  75, tot); }
    { int tot = 3*72*4096;  prep_w<<<(tot+255)/256, 256>>>(w3, w3h, w3l, 256,  9,  8,  72, tot); }
    { int tot = 3*108*4096; prep_w<<<(tot+255)/256, 256>>>(w4, w4h, w4l, 384,  9, 12, 108, tot); }
    { int tot = 2*108*4096; prep_w<<<(tot+255)/256, 256>>>(w5, w5h, w5l, 384,  9, 12, 108, tot); }

    // input -> CHWN split-bf16
    to_chwn227<<<dim3(227, 3), 256, 227*65*4>>>(x, xc1h, xc1l);
    // conv1 (mma) -> CHWN fp32
    mconv1<<<dim3(55*28, 1), 256, 65536>>>(xc1h, xc1l, w1h, w1l, b1, zb, a1t);
    // pool1 -> conv2 input (halo2)
    { int t = 96*27*27*64; pool1_chwn<<<(t+255)/256, 256>>>(a1t, xt2h, xt2l, t); }
    // conv2 (mma) -> fp32 CHWN
    mconv2<96,5,27,2,0><<<dim3(27*14, 2), 256, 65536>>>(xt2h, xt2l, w2h, w2l, b2, nullptr, nullptr, a2t);
    // pool2 -> conv3 input (halo1)
    { int t = 256*13*13*64; pool2_chwn<<<(t+255)/256, 256>>>(a2t, xt3h, xt3l, t); }
    // conv3/4/5 (mma)
    mconv2<256,3,13,1,1><<<dim3(13*7, 3), 256, 65536>>>(xt3h, xt3l, w3h, w3l, b3, xt4h, xt4l, nullptr);
    mconv2<384,3,13,1,1><<<dim3(13*7, 3), 256, 65536>>>(xt4h, xt4l, w4h, w4l, b4, xt5h, xt5l, nullptr);
    mconv2<384,3,13,1,0><<<dim3(13*7, 2), 256, 65536>>>(xt5h, xt5l, w5h, w5l, b5, nullptr, nullptr, a5t);
    // pool3 -> NCHW flatten
    { int t = 64*256*36; pool3_chwn<<<(t+255)/256, 256>>>(a5t, p3, t); }

    // FC
    fc_big<<<dim3(32, 1, 8), 128>>>(p3, fw1, part, 9216, 4096, 8);
    fc_reduce<<<(64*4096 + 255)/256, 256>>>(part, fb1, f1, 4096, 8, 64*4096);
    fc_big<<<dim3(32, 1, 8), 128>>>(f1, fw2, part, 4096, 4096, 8);
    fc_reduce<<<(64*4096 + 255)/256, 256>>>(part, fb2, f2, 4096, 8, 64*4096);
    fc_big<<<dim3(8, 1, 8), 128>>>(f2, fw3, part, 4096, 1000, 8);
    fc_reduce<<<(64*1000 + 255)/256, 256>>>(part, fb3, out, 1000, 8, 64*1000);
}